// round 1
// baseline (speedup 1.0000x reference)
#include <cuda_runtime.h>
#include <math.h>

#define DM   512
#define NH   8
#define DK   64
#define DFF  2048
#define NB   2
#define SQ   2048
#define RT   (NB*SQ)        // 4096 total rows
#define EPSF 1e-6f

// ---------------- scratch (device globals; no runtime allocation) ----------------
__device__ float g_x  [RT*DM];
__device__ float g_x2 [RT*DM];
__device__ float g_q  [RT*DM];
__device__ float g_k  [RT*DM];
__device__ float g_v  [RT*DM];
__device__ float g_ctx[RT*DM];
__device__ float g_ff [RT*DFF];
__device__ float g_sc [(size_t)NB*NH*SQ*SQ];   // 256 MiB attention scores

// ---------------- generic tiled SGEMM ----------------
// C = A * op(B) (+bias)(+relu | +residual). 256 threads.
// FUSE: 0=none, 1=bias, 2=bias+relu, 3=bias+residual
template<int BM,int BN,int BK,int TM,int TN,bool TRB,int FUSE>
__global__ __launch_bounds__(256) void gemm_k(
    const float* __restrict__ A, const float* __restrict__ B, float* __restrict__ C,
    const float* __restrict__ bias, const float* __restrict__ res,
    int K, int lda, int ldb, int ldc,
    long long sAb, long long sAh, long long sBb, long long sBh,
    long long sCb, long long sCh)
{
    __shared__ float As[BK][BM+4];
    __shared__ float Bs[BK][BN+4];

    const int bz = blockIdx.z;
    const int b  = bz / NH, h = bz % NH;
    A += b*sAb + h*sAh;
    B += b*sBb + h*sBh;
    C += b*sCb + h*sCh;

    const int tid = threadIdx.x;
    const int TXC = BN/TN;                 // threads along N
    const int tx = tid % TXC, ty = tid / TXC;
    const int row0 = blockIdx.y*BM, col0 = blockIdx.x*BN;

    float acc[TM][TN];
    #pragma unroll
    for (int i=0;i<TM;i++)
        #pragma unroll
        for (int j=0;j<TN;j++) acc[i][j]=0.f;

    // loader index maps (float4 per thread)
    const int AL  = BM*BK/4;
    const int BL  = (TRB ? BN*BK : BK*BN)/4;
    int ar=0, ac=0, br=0, bc=0;
    if (tid < AL) { ar = tid/(BK/4); ac = (tid%(BK/4))*4; }
    if (tid < BL) {
        if (TRB) { br = tid/(BK/4); bc = (tid%(BK/4))*4; }
        else     { br = tid/(BN/4); bc = (tid%(BN/4))*4; }
    }

    for (int k0 = 0; k0 < K; k0 += BK) {
        if (tid < AL) {
            float4 v = *(const float4*)(A + (long long)(row0+ar)*lda + k0 + ac);
            As[ac+0][ar]=v.x; As[ac+1][ar]=v.y; As[ac+2][ar]=v.z; As[ac+3][ar]=v.w;
        }
        if (tid < BL) {
            if (TRB) {
                float4 v = *(const float4*)(B + (long long)(col0+br)*ldb + k0 + bc);
                Bs[bc+0][br]=v.x; Bs[bc+1][br]=v.y; Bs[bc+2][br]=v.z; Bs[bc+3][br]=v.w;
            } else {
                float4 v = *(const float4*)(B + (long long)(k0+br)*ldb + col0 + bc);
                *(float4*)&Bs[br][bc] = v;
            }
        }
        __syncthreads();
        #pragma unroll
        for (int kk=0; kk<BK; kk++) {
            float a[TM], bb[TN];
            #pragma unroll
            for (int i=0;i<TM;i+=4) *(float4*)&a[i]  = *(const float4*)&As[kk][ty*TM+i];
            #pragma unroll
            for (int j=0;j<TN;j+=4) *(float4*)&bb[j] = *(const float4*)&Bs[kk][tx*TN+j];
            #pragma unroll
            for (int i=0;i<TM;i++)
                #pragma unroll
                for (int j=0;j<TN;j++)
                    acc[i][j] = fmaf(a[i], bb[j], acc[i][j]);
        }
        __syncthreads();
    }

    #pragma unroll
    for (int i=0;i<TM;i++) {
        const int r = row0 + ty*TM + i;
        #pragma unroll
        for (int j0=0;j0<TN;j0+=4) {
            float4 o;
            float* op = &o.x;
            #pragma unroll
            for (int j=0;j<4;j++) {
                const int c = col0 + tx*TN + j0 + j;
                float v = acc[i][j0+j];
                if (FUSE>=1) v += bias[c];
                if (FUSE==2) v = fmaxf(v, 0.f);
                if (FUSE==3) v += res[(long long)r*ldc + c];
                op[j] = v;
            }
            *(float4*)(C + (long long)r*ldc + col0 + tx*TN + j0) = o;
        }
    }
}

// ---------------- LayerNorm (torch-style: unbiased std, div by (sd+eps)) ----------------
__global__ __launch_bounds__(256) void ln_k(const float* __restrict__ in,
                                            const float* __restrict__ al,
                                            const float* __restrict__ be,
                                            float* __restrict__ out)
{
    __shared__ float r1[8], r2[8];
    const long long base = (long long)blockIdx.x * DM;
    const int t = threadIdx.x;
    float2 v = *(const float2*)(in + base + t*2);
    float s = v.x + v.y;
    #pragma unroll
    for (int o=16;o;o>>=1) s += __shfl_xor_sync(0xffffffffu, s, o);
    if ((t&31)==0) r1[t>>5] = s;
    __syncthreads();
    float tot = 0.f;
    #pragma unroll
    for (int w=0;w<8;w++) tot += r1[w];
    const float mu = tot * (1.f/DM);

    const float d0 = v.x - mu, d1 = v.y - mu;
    float ss = d0*d0 + d1*d1;
    #pragma unroll
    for (int o=16;o;o>>=1) ss += __shfl_xor_sync(0xffffffffu, ss, o);
    if ((t&31)==0) r2[t>>5] = ss;
    __syncthreads();
    float tot2 = 0.f;
    #pragma unroll
    for (int w=0;w<8;w++) tot2 += r2[w];
    const float sd  = sqrtf(tot2 * (1.f/(DM-1)));
    const float inv = 1.f/(sd + EPSF);

    float a0 = al[t*2], a1 = al[t*2+1];
    float b0 = be[t*2], b1 = be[t*2+1];
    float2 o2 = make_float2(a0*d0*inv + b0, a1*d1*inv + b1);
    *(float2*)(out + base + t*2) = o2;
}

// ---------------- softmax row kernel; reference mask semantics ----------------
// s_scaled = s/8 ; (causal: j>q -> -inf) ; any exact 0 -> -inf ; softmax
__global__ __launch_bounds__(256) void softmax_k(float* __restrict__ Sp, int causal)
{
    const int q = blockIdx.x;
    float* row = Sp + ((long long)blockIdx.y*SQ + q)*SQ;
    const int t = threadIdx.x;
    __shared__ float r1[8], r2[8];

    float vals[8];
    float mx = -INFINITY;
    #pragma unroll
    for (int i=0;i<8;i++) {
        const int j = t + i*256;
        float v = row[j]*0.125f;
        if ((causal && j>q) || v==0.f) v = -INFINITY;
        vals[i] = v;
        mx = fmaxf(mx, v);
    }
    #pragma unroll
    for (int o=16;o;o>>=1) mx = fmaxf(mx, __shfl_xor_sync(0xffffffffu, mx, o));
    if ((t&31)==0) r1[t>>5] = mx;
    __syncthreads();
    float m = r1[0];
    #pragma unroll
    for (int w=1;w<8;w++) m = fmaxf(m, r1[w]);

    float sum = 0.f;
    #pragma unroll
    for (int i=0;i<8;i++) { float e = __expf(vals[i]-m); vals[i]=e; sum+=e; }
    #pragma unroll
    for (int o=16;o;o>>=1) sum += __shfl_xor_sync(0xffffffffu, sum, o);
    if ((t&31)==0) r2[t>>5] = sum;
    __syncthreads();
    float tot = 0.f;
    #pragma unroll
    for (int w=0;w<8;w++) tot += r2[w];
    const float inv = 1.f/tot;
    #pragma unroll
    for (int i=0;i<8;i++) row[t + i*256] = vals[i]*inv;
}

__global__ void copy_k(const float* __restrict__ a, float* __restrict__ b)
{
    const int i = blockIdx.x*blockDim.x + threadIdx.x;
    ((float4*)b)[i] = ((const float4*)a)[i];
}

// ---------------- launch ----------------
extern "C" void kernel_launch(void* const* d_in, const int* in_sizes, int n_in,
                              void* d_out, int out_size)
{
    const float* x    = (const float*)d_in[0];
    const float* mem  = (const float*)d_in[1];
    const float* ln1a = (const float*)d_in[2];
    const float* ln1b = (const float*)d_in[3];
    const float* ln2a = (const float*)d_in[4];
    const float* ln2b = (const float*)d_in[5];
    const float* ln3a = (const float*)d_in[6];
    const float* ln3b = (const float*)d_in[7];
    const float* wq1  = (const float*)d_in[8];
    const float* wk1  = (const float*)d_in[9];
    const float* wv1  = (const float*)d_in[10];
    const float* wo1  = (const float*)d_in[11];
    const float* bo1  = (const float*)d_in[12];
    const float* wq2  = (const float*)d_in[13];
    const float* wk2  = (const float*)d_in[14];
    const float* wv2  = (const float*)d_in[15];
    const float* wo2  = (const float*)d_in[16];
    const float* bo2  = (const float*)d_in[17];
    const float* fw1  = (const float*)d_in[18];
    const float* fb1  = (const float*)d_in[19];
    const float* fw2  = (const float*)d_in[20];
    const float* fb2  = (const float*)d_in[21];
    float* out = (float*)d_out;

    float *px,*px2,*pq,*pk,*pv,*pctx,*pff,*psc;
    cudaGetSymbolAddress((void**)&px,  g_x);
    cudaGetSymbolAddress((void**)&px2, g_x2);
    cudaGetSymbolAddress((void**)&pq,  g_q);
    cudaGetSymbolAddress((void**)&pk,  g_k);
    cudaGetSymbolAddress((void**)&pv,  g_v);
    cudaGetSymbolAddress((void**)&pctx,g_ctx);
    cudaGetSymbolAddress((void**)&pff, g_ff);
    cudaGetSymbolAddress((void**)&psc, g_sc);

    const long long sQ  = (long long)SQ*DM;       // per-batch stride of q/k/v/ctx rows
    const long long sSC = (long long)SQ*SQ;       // per-head score stride

    const dim3 gProj(4, 32, 1);                   // 4096 x 512
    const dim3 gScores(16, 16, NB*NH);            // 2048 x 2048 per (b,h)
    const dim3 gCtx(1, 16, NB*NH);                // 2048 x 64 per (b,h)
    const dim3 gFF1(16, 32, 1);                   // 4096 x 2048
    const dim3 gSm(SQ, NB*NH);

    copy_k<<<2048, 256>>>(x, px);

    // ---- self attention ----
    ln_k<<<RT, 256>>>(px, ln1a, ln1b, px2);
    gemm_k<128,128,8,8,8,false,0><<<gProj,256>>>(px2, wq1, pq, nullptr,nullptr, DM, DM,DM,DM, 0,0,0,0,0,0);
    gemm_k<128,128,8,8,8,false,0><<<gProj,256>>>(px2, wk1, pk, nullptr,nullptr, DM, DM,DM,DM, 0,0,0,0,0,0);
    gemm_k<128,128,8,8,8,false,0><<<gProj,256>>>(px2, wv1, pv, nullptr,nullptr, DM, DM,DM,DM, 0,0,0,0,0,0);
    gemm_k<128,128,8,8,8,true ,0><<<gScores,256>>>(pq, pk, psc, nullptr,nullptr, DK, DM,DM,SQ,
        sQ, DK, sQ, DK, (long long)NH*sSC, sSC);
    softmax_k<<<gSm,256>>>(psc, 1);
    gemm_k<128,64,8,8,4,false,0><<<gCtx,256>>>(psc, pv, pctx, nullptr,nullptr, SQ, SQ,DM,DM,
        (long long)NH*sSC, sSC, sQ, DK, sQ, DK);
    gemm_k<128,128,8,8,8,false,3><<<gProj,256>>>(pctx, wo1, px, bo1, px, DM, DM,DM,DM, 0,0,0,0,0,0);

    // ---- cross attention ----
    ln_k<<<RT, 256>>>(px, ln2a, ln2b, px2);
    gemm_k<128,128,8,8,8,false,0><<<gProj,256>>>(px2, wq2, pq, nullptr,nullptr, DM, DM,DM,DM, 0,0,0,0,0,0);
    gemm_k<128,128,8,8,8,false,0><<<gProj,256>>>(mem, wk2, pk, nullptr,nullptr, DM, DM,DM,DM, 0,0,0,0,0,0);
    gemm_k<128,128,8,8,8,false,0><<<gProj,256>>>(mem, wv2, pv, nullptr,nullptr, DM, DM,DM,DM, 0,0,0,0,0,0);
    gemm_k<128,128,8,8,8,true ,0><<<gScores,256>>>(pq, pk, psc, nullptr,nullptr, DK, DM,DM,SQ,
        sQ, DK, sQ, DK, (long long)NH*sSC, sSC);
    softmax_k<<<gSm,256>>>(psc, 0);
    gemm_k<128,64,8,8,4,false,0><<<gCtx,256>>>(psc, pv, pctx, nullptr,nullptr, SQ, SQ,DM,DM,
        (long long)NH*sSC, sSC, sQ, DK, sQ, DK);
    gemm_k<128,128,8,8,8,false,3><<<gProj,256>>>(pctx, wo2, px, bo2, px, DM, DM,DM,DM, 0,0,0,0,0,0);

    // ---- feed forward ----
    ln_k<<<RT, 256>>>(px, ln3a, ln3b, px2);
    gemm_k<128,128,8,8,8,false,2><<<gFF1,256>>>(px2, fw1, pff, fb1, nullptr, DM, DM,DFF,DFF, 0,0,0,0,0,0);
    gemm_k<128,128,8,8,8,false,3><<<gProj,256>>>(pff, fw2, out, fb2, px, DFF, DFF,DM,DM, 0,0,0,0,0,0);
}

// round 2
// speedup vs baseline: 2.6225x; 2.6225x over previous
#include <cuda_runtime.h>
#include <math.h>
#include <stdint.h>

#define DM   512
#define NH   8
#define DK   64
#define DFF  2048
#define NB   2
#define SQ   2048
#define RT   (NB*SQ)
#define EPSF 1e-6f

// ---------------- scratch ----------------
__device__ float g_x  [RT*DM];
__device__ float g_x2 [RT*DM];
__device__ float g_q  [RT*DM];
__device__ float g_k  [RT*DM];
__device__ float g_v  [RT*DM];
__device__ float g_ctx[RT*DM];
__device__ float g_ff [RT*DFF];
__device__ float g_sc [(size_t)NB*NH*SQ*SQ];

__device__ __forceinline__ uint32_t f2tf(float f) {
    uint32_t u; asm("cvt.rna.tf32.f32 %0, %1;" : "=r"(u) : "f"(f)); return u;
}

// ---------------- tf32 tensor-core GEMM ----------------
// C = A * op(B) with optional bias/relu/residual.
// TRB=false: B is [K,N] row-major. TRB=true: B is [N,K] row-major (computes A*B^T).
// FUSE: 0=none, 2=bias+relu, 3=bias+residual
template<int BM,int BN,int WM,int WN,bool TRB,int FUSE>
__global__ void __launch_bounds__((BM/WM)*(BN/WN)*32, 2)
tgemm(const float* __restrict__ A, const float* __restrict__ B, float* __restrict__ C,
      const float* __restrict__ bias, const float* __restrict__ res,
      int K, int lda, int ldb, int ldc,
      long long sAb, long long sAh, long long sBb, long long sBh,
      long long sCb, long long sCh)
{
    constexpr int BK   = 16;
    constexpr int WNC  = BN/WN;
    constexpr int WARPS= (BM/WM)*WNC;
    constexpr int T    = WARPS*32;
    constexpr int MT   = WM/16;
    constexpr int NT   = WN/8;
    constexpr int ASTR = BK+4;                      // 20 -> conflict-free frag loads
    constexpr int BROWS= TRB ? BN : BK;
    constexpr int BSTR = TRB ? (BK+4) : (BN+8);
    constexpr int AV   = BM*BK/4/T;                 // float4 loads per thread (A)
    constexpr int BV   = BK*BN/4/T;                 // float4 loads per thread (B)

    __shared__ uint32_t As[2][BM][ASTR];
    __shared__ uint32_t Bs[2][BROWS][BSTR];

    const int bz = blockIdx.z;
    const int b  = bz / NH, h = bz % NH;
    A += b*sAb + h*sAh;
    B += b*sBb + h*sBh;
    C += b*sCb + h*sCh;

    const int tid  = threadIdx.x;
    const int lane = tid & 31;
    const int wid  = tid >> 5;
    const int wm   = wid / WNC, wn = wid % WNC;
    const int row0 = blockIdx.y*BM, col0 = blockIdx.x*BN;

    float acc[MT][NT][4];
    #pragma unroll
    for (int i=0;i<MT;i++)
        #pragma unroll
        for (int j=0;j<NT;j++)
            #pragma unroll
            for (int q=0;q<4;q++) acc[i][j][q]=0.f;

    float4 aReg[AV], bReg[BV];

    auto loadG = [&](int k0) {
        #pragma unroll
        for (int i=0;i<AV;i++) {
            int idx = tid + i*T, r = idx>>2, cv = idx&3;
            aReg[i] = *(const float4*)(A + (long long)(row0+r)*lda + k0 + cv*4);
        }
        #pragma unroll
        for (int i=0;i<BV;i++) {
            int idx = tid + i*T;
            if (TRB) { int r = idx>>2, cv = idx&3;
                bReg[i] = *(const float4*)(B + (long long)(col0+r)*ldb + k0 + cv*4);
            } else   { int r = idx/(BN/4), cv = idx%(BN/4);
                bReg[i] = *(const float4*)(B + (long long)(k0+r)*ldb + col0 + cv*4);
            }
        }
    };
    auto storeS = [&](int bufI) {
        #pragma unroll
        for (int i=0;i<AV;i++) {
            int idx = tid + i*T, r = idx>>2, c = (idx&3)*4;
            As[bufI][r][c+0]=f2tf(aReg[i].x); As[bufI][r][c+1]=f2tf(aReg[i].y);
            As[bufI][r][c+2]=f2tf(aReg[i].z); As[bufI][r][c+3]=f2tf(aReg[i].w);
        }
        #pragma unroll
        for (int i=0;i<BV;i++) {
            int idx = tid + i*T;
            if (TRB) { int r = idx>>2, c = (idx&3)*4;
                Bs[bufI][r][c+0]=f2tf(bReg[i].x); Bs[bufI][r][c+1]=f2tf(bReg[i].y);
                Bs[bufI][r][c+2]=f2tf(bReg[i].z); Bs[bufI][r][c+3]=f2tf(bReg[i].w);
            } else   { int r = idx/(BN/4), c = (idx%(BN/4))*4;
                Bs[bufI][r][c+0]=f2tf(bReg[i].x); Bs[bufI][r][c+1]=f2tf(bReg[i].y);
                Bs[bufI][r][c+2]=f2tf(bReg[i].z); Bs[bufI][r][c+3]=f2tf(bReg[i].w);
            }
        }
    };
    auto compute = [&](int bufI) {
        #pragma unroll
        for (int ks=0; ks<BK; ks+=8) {
            uint32_t af[MT][4], bf[NT][2];
            #pragma unroll
            for (int mt=0; mt<MT; mt++) {
                int r = wm*WM + mt*16 + (lane>>2);
                int c = ks + (lane&3);
                af[mt][0]=As[bufI][r  ][c  ]; af[mt][1]=As[bufI][r+8][c  ];
                af[mt][2]=As[bufI][r  ][c+4]; af[mt][3]=As[bufI][r+8][c+4];
            }
            #pragma unroll
            for (int nt=0; nt<NT; nt++) {
                int n = wn*WN + nt*8 + (lane>>2);
                int k = ks + (lane&3);
                if (TRB) { bf[nt][0]=Bs[bufI][n][k];   bf[nt][1]=Bs[bufI][n][k+4]; }
                else     { bf[nt][0]=Bs[bufI][k][n];   bf[nt][1]=Bs[bufI][k+4][n]; }
            }
            #pragma unroll
            for (int mt=0; mt<MT; mt++)
                #pragma unroll
                for (int nt=0; nt<NT; nt++) {
                    asm volatile(
                      "mma.sync.aligned.m16n8k8.row.col.f32.tf32.tf32.f32 "
                      "{%0,%1,%2,%3}, {%4,%5,%6,%7}, {%8,%9}, {%0,%1,%2,%3};"
                      : "+f"(acc[mt][nt][0]), "+f"(acc[mt][nt][1]),
                        "+f"(acc[mt][nt][2]), "+f"(acc[mt][nt][3])
                      : "r"(af[mt][0]), "r"(af[mt][1]), "r"(af[mt][2]), "r"(af[mt][3]),
                        "r"(bf[nt][0]), "r"(bf[nt][1]));
                }
        }
    };

    loadG(0); storeS(0); __syncthreads();
    int buf = 0;
    for (int k0 = BK; k0 < K; k0 += BK) {
        loadG(k0);
        compute(buf);
        storeS(buf^1);
        __syncthreads();
        buf ^= 1;
    }
    compute(buf);

    // epilogue
    #pragma unroll
    for (int mt=0; mt<MT; mt++) {
        #pragma unroll
        for (int nt=0; nt<NT; nt++) {
            int r = row0 + wm*WM + mt*16 + (lane>>2);
            int c = col0 + wn*WN + nt*8 + (lane&3)*2;
            float v0 = acc[mt][nt][0], v1 = acc[mt][nt][1];
            float v2 = acc[mt][nt][2], v3 = acc[mt][nt][3];
            if (FUSE >= 1) {
                float b0 = bias[c], b1 = bias[c+1];
                v0 += b0; v1 += b1; v2 += b0; v3 += b1;
            }
            if (FUSE == 2) {
                v0 = fmaxf(v0,0.f); v1 = fmaxf(v1,0.f);
                v2 = fmaxf(v2,0.f); v3 = fmaxf(v3,0.f);
            }
            if (FUSE == 3) {
                float2 r0 = *(const float2*)(res + (long long)r*ldc + c);
                float2 r1 = *(const float2*)(res + (long long)(r+8)*ldc + c);
                v0 += r0.x; v1 += r0.y; v2 += r1.x; v3 += r1.y;
            }
            *(float2*)(C + (long long)r*ldc + c)     = make_float2(v0, v1);
            *(float2*)(C + (long long)(r+8)*ldc + c) = make_float2(v2, v3);
        }
    }
}

// ---------------- LayerNorm ----------------
__global__ __launch_bounds__(256) void ln_k(const float* __restrict__ in,
                                            const float* __restrict__ al,
                                            const float* __restrict__ be,
                                            float* __restrict__ out)
{
    __shared__ float r1[8], r2[8];
    const long long base = (long long)blockIdx.x * DM;
    const int t = threadIdx.x;
    float2 v = *(const float2*)(in + base + t*2);
    float s = v.x + v.y;
    #pragma unroll
    for (int o=16;o;o>>=1) s += __shfl_xor_sync(0xffffffffu, s, o);
    if ((t&31)==0) r1[t>>5] = s;
    __syncthreads();
    float tot = 0.f;
    #pragma unroll
    for (int w=0;w<8;w++) tot += r1[w];
    const float mu = tot * (1.f/DM);

    const float d0 = v.x - mu, d1 = v.y - mu;
    float ss = d0*d0 + d1*d1;
    #pragma unroll
    for (int o=16;o;o>>=1) ss += __shfl_xor_sync(0xffffffffu, ss, o);
    if ((t&31)==0) r2[t>>5] = ss;
    __syncthreads();
    float tot2 = 0.f;
    #pragma unroll
    for (int w=0;w<8;w++) tot2 += r2[w];
    const float sd  = sqrtf(tot2 * (1.f/(DM-1)));
    const float inv = 1.f/(sd + EPSF);

    float a0 = al[t*2], a1 = al[t*2+1];
    float b0 = be[t*2], b1 = be[t*2+1];
    *(float2*)(out + base + t*2) = make_float2(a0*d0*inv + b0, a1*d1*inv + b1);
}

// ---------------- softmax (reference mask semantics) ----------------
__global__ __launch_bounds__(256) void softmax_k(float* __restrict__ Sp, int causal)
{
    const int q = blockIdx.x;
    float* row = Sp + ((long long)blockIdx.y*SQ + q)*SQ;
    const int t = threadIdx.x;
    __shared__ float r1[8], r2[8];

    float vals[8];
    float mx = -INFINITY;
    #pragma unroll
    for (int i=0;i<8;i++) {
        const int j = t + i*256;
        float v = row[j]*0.125f;
        if ((causal && j>q) || v==0.f) v = -INFINITY;
        vals[i] = v;
        mx = fmaxf(mx, v);
    }
    #pragma unroll
    for (int o=16;o;o>>=1) mx = fmaxf(mx, __shfl_xor_sync(0xffffffffu, mx, o));
    if ((t&31)==0) r1[t>>5] = mx;
    __syncthreads();
    float m = r1[0];
    #pragma unroll
    for (int w=1;w<8;w++) m = fmaxf(m, r1[w]);

    float sum = 0.f;
    #pragma unroll
    for (int i=0;i<8;i++) { float e = __expf(vals[i]-m); vals[i]=e; sum+=e; }
    #pragma unroll
    for (int o=16;o;o>>=1) sum += __shfl_xor_sync(0xffffffffu, sum, o);
    if ((t&31)==0) r2[t>>5] = sum;
    __syncthreads();
    float tot = 0.f;
    #pragma unroll
    for (int w=0;w<8;w++) tot += r2[w];
    const float inv = 1.f/tot;
    #pragma unroll
    for (int i=0;i<8;i++) row[t + i*256] = vals[i]*inv;
}

__global__ void copy_k(const float* __restrict__ a, float* __restrict__ b)
{
    const int i = blockIdx.x*blockDim.x + threadIdx.x;
    ((float4*)b)[i] = ((const float4*)a)[i];
}

// ---------------- launch ----------------
extern "C" void kernel_launch(void* const* d_in, const int* in_sizes, int n_in,
                              void* d_out, int out_size)
{
    const float* x    = (const float*)d_in[0];
    const float* mem  = (const float*)d_in[1];
    const float* ln1a = (const float*)d_in[2];
    const float* ln1b = (const float*)d_in[3];
    const float* ln2a = (const float*)d_in[4];
    const float* ln2b = (const float*)d_in[5];
    const float* ln3a = (const float*)d_in[6];
    const float* ln3b = (const float*)d_in[7];
    const float* wq1  = (const float*)d_in[8];
    const float* wk1  = (const float*)d_in[9];
    const float* wv1  = (const float*)d_in[10];
    const float* wo1  = (const float*)d_in[11];
    const float* bo1  = (const float*)d_in[12];
    const float* wq2  = (const float*)d_in[13];
    const float* wk2  = (const float*)d_in[14];
    const float* wv2  = (const float*)d_in[15];
    const float* wo2  = (const float*)d_in[16];
    const float* bo2  = (const float*)d_in[17];
    const float* fw1  = (const float*)d_in[18];
    const float* fb1  = (const float*)d_in[19];
    const float* fw2  = (const float*)d_in[20];
    const float* fb2  = (const float*)d_in[21];
    float* out = (float*)d_out;

    float *px,*px2,*pq,*pk,*pv,*pctx,*pff,*psc;
    cudaGetSymbolAddress((void**)&px,  g_x);
    cudaGetSymbolAddress((void**)&px2, g_x2);
    cudaGetSymbolAddress((void**)&pq,  g_q);
    cudaGetSymbolAddress((void**)&pk,  g_k);
    cudaGetSymbolAddress((void**)&pv,  g_v);
    cudaGetSymbolAddress((void**)&pctx,g_ctx);
    cudaGetSymbolAddress((void**)&pff, g_ff);
    cudaGetSymbolAddress((void**)&psc, g_sc);

    const long long sQ  = (long long)SQ*DM;
    const long long sSC = (long long)SQ*SQ;

    // proj / out-proj / ffn2: 4096x512, BN=64 -> 256 blocks of 128 thr
    const dim3 gProj(8, 32, 1);
    const dim3 gScores(16, 16, NB*NH);   // 2048x2048 per (b,h)
    const dim3 gCtx(1, 16, NB*NH);       // 2048x64 per (b,h)
    const dim3 gFF1(16, 32, 1);          // 4096x2048
    const dim3 gSm(SQ, NB*NH);

    copy_k<<<2048, 256>>>(x, px);

    // ---- self attention ----
    ln_k<<<RT, 256>>>(px, ln1a, ln1b, px2);
    tgemm<128,64,64,32,false,0><<<gProj,128>>>(px2, wq1, pq, nullptr,nullptr, DM, DM,DM,DM, 0,0,0,0,0,0);
    tgemm<128,64,64,32,false,0><<<gProj,128>>>(px2, wk1, pk, nullptr,nullptr, DM, DM,DM,DM, 0,0,0,0,0,0);
    tgemm<128,64,64,32,false,0><<<gProj,128>>>(px2, wv1, pv, nullptr,nullptr, DM, DM,DM,DM, 0,0,0,0,0,0);
    tgemm<128,128,64,32,true ,0><<<gScores,256>>>(pq, pk, psc, nullptr,nullptr, DK, DM,DM,SQ,
        sQ, DK, sQ, DK, (long long)NH*sSC, sSC);
    softmax_k<<<gSm,256>>>(psc, 1);
    tgemm<128,64,64,32,false,0><<<gCtx,128>>>(psc, pv, pctx, nullptr,nullptr, SQ, SQ,DM,DM,
        (long long)NH*sSC, sSC, sQ, DK, sQ, DK);
    tgemm<128,64,64,32,false,3><<<gProj,128>>>(pctx, wo1, px, bo1, px, DM, DM,DM,DM, 0,0,0,0,0,0);

    // ---- cross attention ----
    ln_k<<<RT, 256>>>(px, ln2a, ln2b, px2);
    tgemm<128,64,64,32,false,0><<<gProj,128>>>(px2, wq2, pq, nullptr,nullptr, DM, DM,DM,DM, 0,0,0,0,0,0);
    tgemm<128,64,64,32,false,0><<<gProj,128>>>(mem, wk2, pk, nullptr,nullptr, DM, DM,DM,DM, 0,0,0,0,0,0);
    tgemm<128,64,64,32,false,0><<<gProj,128>>>(mem, wv2, pv, nullptr,nullptr, DM, DM,DM,DM, 0,0,0,0,0,0);
    tgemm<128,128,64,32,true ,0><<<gScores,256>>>(pq, pk, psc, nullptr,nullptr, DK, DM,DM,SQ,
        sQ, DK, sQ, DK, (long long)NH*sSC, sSC);
    softmax_k<<<gSm,256>>>(psc, 0);
    tgemm<128,64,64,32,false,0><<<gCtx,128>>>(psc, pv, pctx, nullptr,nullptr, SQ, SQ,DM,DM,
        (long long)NH*sSC, sSC, sQ, DK, sQ, DK);
    tgemm<128,64,64,32,false,3><<<gProj,128>>>(pctx, wo2, px, bo2, px, DM, DM,DM,DM, 0,0,0,0,0,0);

    // ---- feed forward ----
    ln_k<<<RT, 256>>>(px, ln3a, ln3b, px2);
    tgemm<128,128,64,32,false,2><<<gFF1,256>>>(px2, fw1, pff, fb1, nullptr, DM, DM,DFF,DFF, 0,0,0,0,0,0);
    tgemm<128,64,64,32,false,3><<<gProj,128>>>(pff, fw2, out, fb2, px, DFF, DFF,DM,DM, 0,0,0,0,0,0);
}

// round 3
// speedup vs baseline: 3.8206x; 1.4568x over previous
#include <cuda_runtime.h>
#include <math.h>
#include <stdint.h>

#define DM   512
#define NH   8
#define DK   64
#define DFF  2048
#define NB   2
#define SQ   2048
#define RT   (NB*SQ)
#define EPSF 1e-6f

// ---------------- scratch ----------------
__device__ float g_x  [RT*DM];
__device__ float g_x2 [RT*DM];
__device__ float g_q  [RT*DM];
__device__ float g_k  [RT*DM];
__device__ float g_v  [RT*DM];
__device__ float g_ctx[RT*DM];
__device__ float g_ff [RT*DFF];

__device__ __forceinline__ uint32_t f2tf(float f) {
    uint32_t u; asm("cvt.rna.tf32.f32 %0, %1;" : "=r"(u) : "f"(f)); return u;
}

#define MMA_TF32(acc, a0,a1,a2,a3, b0,b1) \
    asm volatile("mma.sync.aligned.m16n8k8.row.col.f32.tf32.tf32.f32 " \
                 "{%0,%1,%2,%3}, {%4,%5,%6,%7}, {%8,%9}, {%0,%1,%2,%3};" \
                 : "+f"(acc[0]), "+f"(acc[1]), "+f"(acc[2]), "+f"(acc[3]) \
                 : "r"(a0), "r"(a1), "r"(a2), "r"(a3), "r"(b0), "r"(b1))

// ---------------- tf32 tensor-core GEMM (projections / FFN) ----------------
template<int BM,int BN,int WM,int WN,bool TRB,int FUSE>
__global__ void __launch_bounds__((BM/WM)*(BN/WN)*32, 2)
tgemm(const float* __restrict__ A, const float* __restrict__ B, float* __restrict__ C,
      const float* __restrict__ bias, const float* __restrict__ res,
      int K, int lda, int ldb, int ldc)
{
    constexpr int BK   = 16;
    constexpr int WNC  = BN/WN;
    constexpr int WARPS= (BM/WM)*WNC;
    constexpr int T    = WARPS*32;
    constexpr int MT   = WM/16;
    constexpr int NT   = WN/8;
    constexpr int ASTR = BK+4;
    constexpr int BROWS= TRB ? BN : BK;
    constexpr int BSTR = TRB ? (BK+4) : (BN+8);
    constexpr int AV   = BM*BK/4/T;
    constexpr int BV   = BK*BN/4/T;

    __shared__ uint32_t As[2][BM][ASTR];
    __shared__ uint32_t Bs[2][BROWS][BSTR];

    const int tid  = threadIdx.x;
    const int lane = tid & 31;
    const int wid  = tid >> 5;
    const int wm   = wid / WNC, wn = wid % WNC;
    const int row0 = blockIdx.y*BM, col0 = blockIdx.x*BN;

    float acc[MT][NT][4];
    #pragma unroll
    for (int i=0;i<MT;i++)
        #pragma unroll
        for (int j=0;j<NT;j++)
            #pragma unroll
            for (int q=0;q<4;q++) acc[i][j][q]=0.f;

    float4 aReg[AV], bReg[BV];

    auto loadG = [&](int k0) {
        #pragma unroll
        for (int i=0;i<AV;i++) {
            int idx = tid + i*T, r = idx>>2, cv = idx&3;
            aReg[i] = *(const float4*)(A + (long long)(row0+r)*lda + k0 + cv*4);
        }
        #pragma unroll
        for (int i=0;i<BV;i++) {
            int idx = tid + i*T;
            if (TRB) { int r = idx>>2, cv = idx&3;
                bReg[i] = *(const float4*)(B + (long long)(col0+r)*ldb + k0 + cv*4);
            } else   { int r = idx/(BN/4), cv = idx%(BN/4);
                bReg[i] = *(const float4*)(B + (long long)(k0+r)*ldb + col0 + cv*4);
            }
        }
    };
    auto storeS = [&](int bufI) {
        #pragma unroll
        for (int i=0;i<AV;i++) {
            int idx = tid + i*T, r = idx>>2, c = (idx&3)*4;
            As[bufI][r][c+0]=f2tf(aReg[i].x); As[bufI][r][c+1]=f2tf(aReg[i].y);
            As[bufI][r][c+2]=f2tf(aReg[i].z); As[bufI][r][c+3]=f2tf(aReg[i].w);
        }
        #pragma unroll
        for (int i=0;i<BV;i++) {
            int idx = tid + i*T;
            if (TRB) { int r = idx>>2, c = (idx&3)*4;
                Bs[bufI][r][c+0]=f2tf(bReg[i].x); Bs[bufI][r][c+1]=f2tf(bReg[i].y);
                Bs[bufI][r][c+2]=f2tf(bReg[i].z); Bs[bufI][r][c+3]=f2tf(bReg[i].w);
            } else   { int r = idx/(BN/4), c = (idx%(BN/4))*4;
                Bs[bufI][r][c+0]=f2tf(bReg[i].x); Bs[bufI][r][c+1]=f2tf(bReg[i].y);
                Bs[bufI][r][c+2]=f2tf(bReg[i].z); Bs[bufI][r][c+3]=f2tf(bReg[i].w);
            }
        }
    };
    auto compute = [&](int bufI) {
        #pragma unroll
        for (int ks=0; ks<BK; ks+=8) {
            uint32_t af[MT][4], bf[NT][2];
            #pragma unroll
            for (int mt=0; mt<MT; mt++) {
                int r = wm*WM + mt*16 + (lane>>2);
                int c = ks + (lane&3);
                af[mt][0]=As[bufI][r  ][c  ]; af[mt][1]=As[bufI][r+8][c  ];
                af[mt][2]=As[bufI][r  ][c+4]; af[mt][3]=As[bufI][r+8][c+4];
            }
            #pragma unroll
            for (int nt=0; nt<NT; nt++) {
                int n = wn*WN + nt*8 + (lane>>2);
                int k = ks + (lane&3);
                if (TRB) { bf[nt][0]=Bs[bufI][n][k];   bf[nt][1]=Bs[bufI][n][k+4]; }
                else     { bf[nt][0]=Bs[bufI][k][n];   bf[nt][1]=Bs[bufI][k+4][n]; }
            }
            #pragma unroll
            for (int mt=0; mt<MT; mt++)
                #pragma unroll
                for (int nt=0; nt<NT; nt++)
                    MMA_TF32(acc[mt][nt], af[mt][0],af[mt][1],af[mt][2],af[mt][3],
                             bf[nt][0], bf[nt][1]);
        }
    };

    loadG(0); storeS(0); __syncthreads();
    int buf = 0;
    for (int k0 = BK; k0 < K; k0 += BK) {
        loadG(k0);
        compute(buf);
        storeS(buf^1);
        __syncthreads();
        buf ^= 1;
    }
    compute(buf);

    #pragma unroll
    for (int mt=0; mt<MT; mt++) {
        #pragma unroll
        for (int nt=0; nt<NT; nt++) {
            int r = row0 + wm*WM + mt*16 + (lane>>2);
            int c = col0 + wn*WN + nt*8 + (lane&3)*2;
            float v0 = acc[mt][nt][0], v1 = acc[mt][nt][1];
            float v2 = acc[mt][nt][2], v3 = acc[mt][nt][3];
            if (FUSE >= 1) {
                float b0 = bias[c], b1 = bias[c+1];
                v0 += b0; v1 += b1; v2 += b0; v3 += b1;
            }
            if (FUSE == 2) {
                v0 = fmaxf(v0,0.f); v1 = fmaxf(v1,0.f);
                v2 = fmaxf(v2,0.f); v3 = fmaxf(v3,0.f);
            }
            if (FUSE == 3) {
                float2 r0 = *(const float2*)(res + (long long)r*ldc + c);
                float2 r1 = *(const float2*)(res + (long long)(r+8)*ldc + c);
                v0 += r0.x; v1 += r0.y; v2 += r1.x; v3 += r1.y;
            }
            *(float2*)(C + (long long)r*ldc + c)     = make_float2(v0, v1);
            *(float2*)(C + (long long)(r+8)*ldc + c) = make_float2(v2, v3);
        }
    }
}

// ---------------- fused flash attention (tf32 MMA, online softmax) ----------------
// Q/K/V/O layout: [b*SQ + row][DM], head h occupies cols h*DK..h*DK+63.
// Semantics: s = (q.k)/8 ; causal j>q -> -inf ; s==0 -> -inf ; softmax ; P.V
#define FBQ  64
#define FBKV 64
#define KSTR 68
#define VSTR 72

template<bool CAUSAL>
__global__ void __launch_bounds__(128, 2)
flash_k(const float* __restrict__ Qg, const float* __restrict__ Kg,
        const float* __restrict__ Vg, float* __restrict__ Og)
{
    __shared__ uint32_t Ks[FBKV][KSTR];
    __shared__ uint32_t Vs[FBKV][VSTR];

    const int bz = blockIdx.y;
    const int b  = bz / NH, h = bz % NH;
    const int qt = blockIdx.x;
    const int tid = threadIdx.x;
    const int lane = tid & 31, w = tid >> 5;
    const int gr = lane >> 2, t = lane & 3;
    const int q0 = qt * FBQ;
    const long long rowB = (long long)b * SQ;
    const int hc = h * DK;

    // ---- Q tile -> smem (pre-scaled by 1/8, tf32), then to register A-frags ----
    #pragma unroll
    for (int i = 0; i < FBQ*DK/4/128; i++) {
        int e = tid + i*128;
        int r = e >> 4, c4 = (e & 15) * 4;
        float4 v = *(const float4*)(Qg + (rowB + q0 + r)*DM + hc + c4);
        Ks[r][c4+0] = f2tf(v.x*0.125f); Ks[r][c4+1] = f2tf(v.y*0.125f);
        Ks[r][c4+2] = f2tf(v.z*0.125f); Ks[r][c4+3] = f2tf(v.w*0.125f);
    }
    __syncthreads();
    uint32_t qa[8][4];
    {
        const int r = w*16 + gr;
        #pragma unroll
        for (int kg = 0; kg < 8; kg++) {
            qa[kg][0] = Ks[r  ][kg*8+t];
            qa[kg][1] = Ks[r+8][kg*8+t];
            qa[kg][2] = Ks[r  ][kg*8+t+4];
            qa[kg][3] = Ks[r+8][kg*8+t+4];
        }
    }
    __syncthreads();

    float o[8][4];
    #pragma unroll
    for (int d=0; d<8; d++) { o[d][0]=0.f; o[d][1]=0.f; o[d][2]=0.f; o[d][3]=0.f; }
    float m0 = -INFINITY, m1 = -INFINITY, l0 = 0.f, l1 = 0.f;
    const int r0l = q0 + w*16 + gr;
    const int r1l = r0l + 8;

    const int nch = CAUSAL ? (qt + 1) : (SQ / FBKV);
    for (int ch = 0; ch < nch; ch++) {
        const int c0 = ch * FBKV;
        #pragma unroll
        for (int i = 0; i < FBKV*DK/4/128; i++) {
            int e = tid + i*128;
            int r = e >> 4, c4 = (e & 15)*4;
            float4 k4 = *(const float4*)(Kg + (rowB + c0 + r)*DM + hc + c4);
            Ks[r][c4+0]=f2tf(k4.x); Ks[r][c4+1]=f2tf(k4.y);
            Ks[r][c4+2]=f2tf(k4.z); Ks[r][c4+3]=f2tf(k4.w);
            float4 v4 = *(const float4*)(Vg + (rowB + c0 + r)*DM + hc + c4);
            Vs[r][c4+0]=f2tf(v4.x); Vs[r][c4+1]=f2tf(v4.y);
            Vs[r][c4+2]=f2tf(v4.z); Vs[r][c4+3]=f2tf(v4.w);
        }
        __syncthreads();

        // ---- S = Q.K^T ----
        float s[8][4];
        #pragma unroll
        for (int nt=0; nt<8; nt++) { s[nt][0]=0.f; s[nt][1]=0.f; s[nt][2]=0.f; s[nt][3]=0.f; }
        #pragma unroll
        for (int kg = 0; kg < 8; kg++) {
            #pragma unroll
            for (int nt = 0; nt < 8; nt++) {
                uint32_t b0 = Ks[nt*8+gr][kg*8+t];
                uint32_t b1 = Ks[nt*8+gr][kg*8+t+4];
                MMA_TF32(s[nt], qa[kg][0],qa[kg][1],qa[kg][2],qa[kg][3], b0, b1);
            }
        }

        // ---- mask + online softmax ----
        float mx0 = -INFINITY, mx1 = -INFINITY;
        #pragma unroll
        for (int nt=0; nt<8; nt++) {
            const int j0 = c0 + nt*8 + 2*t, j1 = j0 + 1;
            float v0=s[nt][0], v1=s[nt][1], v2=s[nt][2], v3=s[nt][3];
            if ((CAUSAL && j0 > r0l) || v0==0.f) v0 = -INFINITY;
            if ((CAUSAL && j1 > r0l) || v1==0.f) v1 = -INFINITY;
            if ((CAUSAL && j0 > r1l) || v2==0.f) v2 = -INFINITY;
            if ((CAUSAL && j1 > r1l) || v3==0.f) v3 = -INFINITY;
            s[nt][0]=v0; s[nt][1]=v1; s[nt][2]=v2; s[nt][3]=v3;
            mx0 = fmaxf(mx0, fmaxf(v0,v1));
            mx1 = fmaxf(mx1, fmaxf(v2,v3));
        }
        mx0 = fmaxf(mx0, __shfl_xor_sync(0xffffffffu, mx0, 1));
        mx0 = fmaxf(mx0, __shfl_xor_sync(0xffffffffu, mx0, 2));
        mx1 = fmaxf(mx1, __shfl_xor_sync(0xffffffffu, mx1, 1));
        mx1 = fmaxf(mx1, __shfl_xor_sync(0xffffffffu, mx1, 2));
        const float mn0 = fmaxf(m0, mx0), mn1 = fmaxf(m1, mx1);
        const float sc0 = __expf(m0 - mn0), sc1 = __expf(m1 - mn1);

        float ps0 = 0.f, ps1 = 0.f;
        #pragma unroll
        for (int nt=0; nt<8; nt++) {
            float p0 = __expf(s[nt][0] - mn0);
            float p1 = __expf(s[nt][1] - mn0);
            float p2 = __expf(s[nt][2] - mn1);
            float p3 = __expf(s[nt][3] - mn1);
            s[nt][0]=p0; s[nt][1]=p1; s[nt][2]=p2; s[nt][3]=p3;
            ps0 += p0 + p1; ps1 += p2 + p3;
        }
        ps0 += __shfl_xor_sync(0xffffffffu, ps0, 1);
        ps0 += __shfl_xor_sync(0xffffffffu, ps0, 2);
        ps1 += __shfl_xor_sync(0xffffffffu, ps1, 1);
        ps1 += __shfl_xor_sync(0xffffffffu, ps1, 2);
        l0 = l0*sc0 + ps0; l1 = l1*sc1 + ps1;
        m0 = mn0; m1 = mn1;
        #pragma unroll
        for (int d=0; d<8; d++) {
            o[d][0]*=sc0; o[d][1]*=sc0; o[d][2]*=sc1; o[d][3]*=sc1;
        }

        // ---- O += P.V : shfl C-layout -> A-layout, then MMA ----
        const int base = lane & ~3;
        #pragma unroll
        for (int kg=0; kg<8; kg++) {
            const int sA = base + (t>>1), sB = sA + 2;
            float xA0 = __shfl_sync(0xffffffffu, s[kg][0], sA);
            float xA1 = __shfl_sync(0xffffffffu, s[kg][1], sA);
            float xA2 = __shfl_sync(0xffffffffu, s[kg][2], sA);
            float xA3 = __shfl_sync(0xffffffffu, s[kg][3], sA);
            float xB0 = __shfl_sync(0xffffffffu, s[kg][0], sB);
            float xB1 = __shfl_sync(0xffffffffu, s[kg][1], sB);
            float xB2 = __shfl_sync(0xffffffffu, s[kg][2], sB);
            float xB3 = __shfl_sync(0xffffffffu, s[kg][3], sB);
            const uint32_t a0 = f2tf((t&1) ? xA1 : xA0);
            const uint32_t a1 = f2tf((t&1) ? xA3 : xA2);
            const uint32_t a2 = f2tf((t&1) ? xB1 : xB0);
            const uint32_t a3 = f2tf((t&1) ? xB3 : xB2);
            #pragma unroll
            for (int d=0; d<8; d++) {
                uint32_t b0 = Vs[kg*8+t  ][d*8+gr];
                uint32_t b1 = Vs[kg*8+t+4][d*8+gr];
                MMA_TF32(o[d], a0,a1,a2,a3, b0, b1);
            }
        }
        __syncthreads();
    }

    const float i0 = 1.f/l0, i1 = 1.f/l1;
    #pragma unroll
    for (int d=0; d<8; d++) {
        const int c = hc + d*8 + 2*t;
        *(float2*)(Og + (rowB + r0l)*DM + c) = make_float2(o[d][0]*i0, o[d][1]*i0);
        *(float2*)(Og + (rowB + r1l)*DM + c) = make_float2(o[d][2]*i1, o[d][3]*i1);
    }
}

// ---------------- LayerNorm ----------------
__global__ __launch_bounds__(256) void ln_k(const float* __restrict__ in,
                                            const float* __restrict__ al,
                                            const float* __restrict__ be,
                                            float* __restrict__ out)
{
    __shared__ float r1[8], r2[8];
    const long long base = (long long)blockIdx.x * DM;
    const int t = threadIdx.x;
    float2 v = *(const float2*)(in + base + t*2);
    float s = v.x + v.y;
    #pragma unroll
    for (int o=16;o;o>>=1) s += __shfl_xor_sync(0xffffffffu, s, o);
    if ((t&31)==0) r1[t>>5] = s;
    __syncthreads();
    float tot = 0.f;
    #pragma unroll
    for (int w=0;w<8;w++) tot += r1[w];
    const float mu = tot * (1.f/DM);

    const float d0 = v.x - mu, d1 = v.y - mu;
    float ss = d0*d0 + d1*d1;
    #pragma unroll
    for (int o=16;o;o>>=1) ss += __shfl_xor_sync(0xffffffffu, ss, o);
    if ((t&31)==0) r2[t>>5] = ss;
    __syncthreads();
    float tot2 = 0.f;
    #pragma unroll
    for (int w=0;w<8;w++) tot2 += r2[w];
    const float sd  = sqrtf(tot2 * (1.f/(DM-1)));
    const float inv = 1.f/(sd + EPSF);

    float a0 = al[t*2], a1 = al[t*2+1];
    float b0 = be[t*2], b1 = be[t*2+1];
    *(float2*)(out + base + t*2) = make_float2(a0*d0*inv + b0, a1*d1*inv + b1);
}

__global__ void copy_k(const float* __restrict__ a, float* __restrict__ b)
{
    const int i = blockIdx.x*blockDim.x + threadIdx.x;
    ((float4*)b)[i] = ((const float4*)a)[i];
}

// ---------------- launch ----------------
extern "C" void kernel_launch(void* const* d_in, const int* in_sizes, int n_in,
                              void* d_out, int out_size)
{
    const float* x    = (const float*)d_in[0];
    const float* mem  = (const float*)d_in[1];
    const float* ln1a = (const float*)d_in[2];
    const float* ln1b = (const float*)d_in[3];
    const float* ln2a = (const float*)d_in[4];
    const float* ln2b = (const float*)d_in[5];
    const float* ln3a = (const float*)d_in[6];
    const float* ln3b = (const float*)d_in[7];
    const float* wq1  = (const float*)d_in[8];
    const float* wk1  = (const float*)d_in[9];
    const float* wv1  = (const float*)d_in[10];
    const float* wo1  = (const float*)d_in[11];
    const float* bo1  = (const float*)d_in[12];
    const float* wq2  = (const float*)d_in[13];
    const float* wk2  = (const float*)d_in[14];
    const float* wv2  = (const float*)d_in[15];
    const float* wo2  = (const float*)d_in[16];
    const float* bo2  = (const float*)d_in[17];
    const float* fw1  = (const float*)d_in[18];
    const float* fb1  = (const float*)d_in[19];
    const float* fw2  = (const float*)d_in[20];
    const float* fb2  = (const float*)d_in[21];
    float* out = (float*)d_out;

    float *px,*px2,*pq,*pk,*pv,*pctx,*pff;
    cudaGetSymbolAddress((void**)&px,  g_x);
    cudaGetSymbolAddress((void**)&px2, g_x2);
    cudaGetSymbolAddress((void**)&pq,  g_q);
    cudaGetSymbolAddress((void**)&pk,  g_k);
    cudaGetSymbolAddress((void**)&pv,  g_v);
    cudaGetSymbolAddress((void**)&pctx,g_ctx);
    cudaGetSymbolAddress((void**)&pff, g_ff);

    const dim3 gProj(8, 32, 1);          // 4096 x 512
    const dim3 gFF1(16, 32, 1);          // 4096 x 2048
    const dim3 gFlash(SQ/FBQ, NB*NH);    // (32, 16)

    copy_k<<<2048, 256>>>(x, px);

    // ---- self attention ----
    ln_k<<<RT, 256>>>(px, ln1a, ln1b, px2);
    tgemm<128,64,64,32,false,0><<<gProj,128>>>(px2, wq1, pq, nullptr,nullptr, DM, DM,DM,DM);
    tgemm<128,64,64,32,false,0><<<gProj,128>>>(px2, wk1, pk, nullptr,nullptr, DM, DM,DM,DM);
    tgemm<128,64,64,32,false,0><<<gProj,128>>>(px2, wv1, pv, nullptr,nullptr, DM, DM,DM,DM);
    flash_k<true><<<gFlash,128>>>(pq, pk, pv, pctx);
    tgemm<128,64,64,32,false,3><<<gProj,128>>>(pctx, wo1, px, bo1, px, DM, DM,DM,DM);

    // ---- cross attention ----
    ln_k<<<RT, 256>>>(px, ln2a, ln2b, px2);
    tgemm<128,64,64,32,false,0><<<gProj,128>>>(px2, wq2, pq, nullptr,nullptr, DM, DM,DM,DM);
    tgemm<128,64,64,32,false,0><<<gProj,128>>>(mem, wk2, pk, nullptr,nullptr, DM, DM,DM,DM);
    tgemm<128,64,64,32,false,0><<<gProj,128>>>(mem, wv2, pv, nullptr,nullptr, DM, DM,DM,DM);
    flash_k<false><<<gFlash,128>>>(pq, pk, pv, pctx);
    tgemm<128,64,64,32,false,3><<<gProj,128>>>(pctx, wo2, px, bo2, px, DM, DM,DM,DM);

    // ---- feed forward ----
    ln_k<<<RT, 256>>>(px, ln3a, ln3b, px2);
    tgemm<128,128,64,32,false,2><<<gFF1,256>>>(px2, fw1, pff, fb1, nullptr, DM, DM,DFF,DFF);
    tgemm<128,64,64,32,false,3><<<gProj,128>>>(pff, fw2, out, fb2, px, DFF, DFF,DM,DM);
}

// round 5
// speedup vs baseline: 3.8594x; 1.0102x over previous
#include <cuda_runtime.h>
#include <math.h>
#include <stdint.h>

#define DM   512
#define NH   8
#define DK   64
#define DFF  2048
#define NB   2
#define SQ   2048
#define RT   (NB*SQ)
#define EPSF 1e-6f

// ---------------- scratch ----------------
__device__ float g_x   [RT*DM];
__device__ float g_x2  [RT*DM];
__device__ float g_q   [RT*DM];
__device__ float g_ctx [RT*DM];
__device__ float g_qkv [RT*3*DM];
__device__ float g_kv  [RT*2*DM];
__device__ float g_ff  [RT*DFF];
__device__ float g_mem [RT*DM];
__device__ float g_wqkv[DM*3*DM];
__device__ float g_wq2 [DM*DM];
__device__ float g_wkv [DM*2*DM];
__device__ float g_wo1 [DM*DM];
__device__ float g_wo2 [DM*DM];
__device__ float g_fw1 [DM*DFF];
__device__ float g_fw2 [DFF*DM];

__device__ __forceinline__ uint32_t f2tf(float f) {
    uint32_t u; asm("cvt.rna.tf32.f32 %0, %1;" : "=r"(u) : "f"(f)); return u;
}
__device__ __forceinline__ float rtf(float f) { return __uint_as_float(f2tf(f)); }

#define MMA_TF32(acc, a0,a1,a2,a3, b0,b1) \
    asm volatile("mma.sync.aligned.m16n8k8.row.col.f32.tf32.tf32.f32 " \
                 "{%0,%1,%2,%3}, {%4,%5,%6,%7}, {%8,%9}, {%0,%1,%2,%3};" \
                 : "+f"(acc[0]), "+f"(acc[1]), "+f"(acc[2]), "+f"(acc[3]) \
                 : "r"(a0), "r"(a1), "r"(a2), "r"(a3), "r"(b0), "r"(b1))

__device__ __forceinline__ void cp16(uint32_t dst, const void* src) {
    asm volatile("cp.async.ca.shared.global [%0], [%1], 16;" :: "r"(dst), "l"(src));
}
#define CP_COMMIT asm volatile("cp.async.commit_group;")
#define CP_WAIT2  asm volatile("cp.async.wait_group 2;")

// ---------------- pipelined tf32 GEMM ----------------
// 128x128x16 tiles, 4-stage cp.async, 256 threads, warp tile 64x32.
// A,B must hold tf32-valued fp32 (pre-rounded). FUSE: 0=none, 2=bias+relu+round, 3=bias+residual
#define GST   4
#define GBK   16
#define ASTR  20
#define BSTR  136
#define GSMEM ((GST*128*ASTR + GST*GBK*BSTR)*4)

template<int FUSE>
__global__ void __launch_bounds__(256, 2)
tgemm(const float* __restrict__ A, const float* __restrict__ B, float* __restrict__ C,
      const float* __restrict__ bias, const float* __restrict__ res,
      int K, int lda, int ldb, int ldc)
{
    extern __shared__ float sm[];
    float* Asm = sm;                          // [GST][128][ASTR]
    float* Bsm = sm + GST*128*ASTR;           // [GST][GBK][BSTR]

    const int tid  = threadIdx.x;
    const int lane = tid & 31;
    const int wid  = tid >> 5;
    const int wm   = wid >> 2, wn = wid & 3;  // 2x4 warps
    const int gr   = lane >> 2, t = lane & 3;
    const int row0 = blockIdx.y*128, col0 = blockIdx.x*128;

    const int ar  = (tid + 0*256) >> 2, ac  = ((tid + 0*256) & 3)*4;
    const int ar2 = (tid + 1*256) >> 2, ac2 = ((tid + 1*256) & 3)*4;
    const int bk  = (tid + 0*256) >> 5, bn  = ((tid + 0*256) & 31)*4;
    const int bk2 = (tid + 1*256) >> 5, bn2 = ((tid + 1*256) & 31)*4;

    auto issue = [&](int s, int k0) {
        float* Ad = Asm + s*128*ASTR;
        float* Bd = Bsm + s*GBK*BSTR;
        cp16((uint32_t)__cvta_generic_to_shared(Ad + ar *ASTR + ac ),
             A + (long long)(row0+ar )*lda + k0 + ac );
        cp16((uint32_t)__cvta_generic_to_shared(Ad + ar2*ASTR + ac2),
             A + (long long)(row0+ar2)*lda + k0 + ac2);
        cp16((uint32_t)__cvta_generic_to_shared(Bd + bk *BSTR + bn ),
             B + (long long)(k0+bk )*ldb + col0 + bn );
        cp16((uint32_t)__cvta_generic_to_shared(Bd + bk2*BSTR + bn2),
             B + (long long)(k0+bk2)*ldb + col0 + bn2);
    };

    float acc[4][4][4];
    #pragma unroll
    for (int i=0;i<4;i++)
        #pragma unroll
        for (int j=0;j<4;j++)
            #pragma unroll
            for (int q=0;q<4;q++) acc[i][j][q]=0.f;

    const int NIT = K / GBK;
    #pragma unroll
    for (int s = 0; s < GST-1; s++) { issue(s, s*GBK); CP_COMMIT; }

    for (int it = 0; it < NIT; it++) {
        CP_WAIT2;
        __syncthreads();
        const int pf = it + GST-1;
        if (pf < NIT) issue(pf % GST, pf*GBK);
        CP_COMMIT;

        const float* As = Asm + (it % GST)*128*ASTR;
        const float* Bs = Bsm + (it % GST)*GBK*BSTR;
        #pragma unroll
        for (int ks = 0; ks < GBK; ks += 8) {
            uint32_t af[4][4], bf[4][2];
            #pragma unroll
            for (int mt=0; mt<4; mt++) {
                const int r = wm*64 + mt*16 + gr;
                const int c = ks + t;
                af[mt][0]=__float_as_uint(As[ r   *ASTR + c  ]);
                af[mt][1]=__float_as_uint(As[(r+8)*ASTR + c  ]);
                af[mt][2]=__float_as_uint(As[ r   *ASTR + c+4]);
                af[mt][3]=__float_as_uint(As[(r+8)*ASTR + c+4]);
            }
            #pragma unroll
            for (int nt=0; nt<4; nt++) {
                const int n = wn*32 + nt*8 + gr;
                const int k = ks + t;
                bf[nt][0]=__float_as_uint(Bs[ k   *BSTR + n]);
                bf[nt][1]=__float_as_uint(Bs[(k+4)*BSTR + n]);
            }
            #pragma unroll
            for (int mt=0; mt<4; mt++)
                #pragma unroll
                for (int nt=0; nt<4; nt++)
                    MMA_TF32(acc[mt][nt], af[mt][0],af[mt][1],af[mt][2],af[mt][3],
                             bf[nt][0], bf[nt][1]);
        }
    }

    #pragma unroll
    for (int mt=0; mt<4; mt++) {
        #pragma unroll
        for (int nt=0; nt<4; nt++) {
            const int r = row0 + wm*64 + mt*16 + gr;
            const int c = col0 + wn*32 + nt*8 + 2*t;
            float v0 = acc[mt][nt][0], v1 = acc[mt][nt][1];
            float v2 = acc[mt][nt][2], v3 = acc[mt][nt][3];
            if (FUSE >= 1) {
                float b0 = bias[c], b1 = bias[c+1];
                v0 += b0; v1 += b1; v2 += b0; v3 += b1;
            }
            if (FUSE == 2) {
                v0 = rtf(fmaxf(v0,0.f)); v1 = rtf(fmaxf(v1,0.f));
                v2 = rtf(fmaxf(v2,0.f)); v3 = rtf(fmaxf(v3,0.f));
            }
            if (FUSE == 3) {
                float2 r0 = *(const float2*)(res + (long long)r*ldc + c);
                float2 r1 = *(const float2*)(res + (long long)(r+8)*ldc + c);
                v0 += r0.x; v1 += r0.y; v2 += r1.x; v3 += r1.y;
            }
            *(float2*)(C + (long long)r*ldc + c)     = make_float2(v0, v1);
            *(float2*)(C + (long long)(r+8)*ldc + c) = make_float2(v2, v3);
        }
    }
}

// ---------------- fused flash attention (tf32 MMA, online softmax) ----------------
#define FBQ  64
#define FBKV 64
#define KSTR 68
#define VSTR 72

template<bool CAUSAL>
__global__ void __launch_bounds__(128, 2)
flash_k(const float* __restrict__ Qg, const float* __restrict__ Kg,
        const float* __restrict__ Vg, float* __restrict__ Og, int ldq, int ldkv)
{
    __shared__ uint32_t Ks[FBKV][KSTR];
    __shared__ uint32_t Vs[FBKV][VSTR];

    const int bz = blockIdx.y;
    const int b  = bz / NH, h = bz % NH;
    const int qt = blockIdx.x;
    const int tid = threadIdx.x;
    const int lane = tid & 31, w = tid >> 5;
    const int gr = lane >> 2, t = lane & 3;
    const int q0 = qt * FBQ;
    const long long rowB = (long long)b * SQ;
    const int hc = h * DK;

    #pragma unroll
    for (int i = 0; i < FBQ*DK/4/128; i++) {
        int e = tid + i*128;
        int r = e >> 4, c4 = (e & 15) * 4;
        float4 v = *(const float4*)(Qg + (rowB + q0 + r)*ldq + hc + c4);
        Ks[r][c4+0] = f2tf(v.x*0.125f); Ks[r][c4+1] = f2tf(v.y*0.125f);
        Ks[r][c4+2] = f2tf(v.z*0.125f); Ks[r][c4+3] = f2tf(v.w*0.125f);
    }
    __syncthreads();
    uint32_t qa[8][4];
    {
        const int r = w*16 + gr;
        #pragma unroll
        for (int kg = 0; kg < 8; kg++) {
            qa[kg][0] = Ks[r  ][kg*8+t];
            qa[kg][1] = Ks[r+8][kg*8+t];
            qa[kg][2] = Ks[r  ][kg*8+t+4];
            qa[kg][3] = Ks[r+8][kg*8+t+4];
        }
    }
    __syncthreads();

    float o[8][4];
    #pragma unroll
    for (int d=0; d<8; d++) { o[d][0]=0.f; o[d][1]=0.f; o[d][2]=0.f; o[d][3]=0.f; }
    float m0 = -INFINITY, m1 = -INFINITY, l0 = 0.f, l1 = 0.f;
    const int r0l = q0 + w*16 + gr;
    const int r1l = r0l + 8;

    const int nch = CAUSAL ? (qt + 1) : (SQ / FBKV);
    for (int ch = 0; ch < nch; ch++) {
        const int c0 = ch * FBKV;
        #pragma unroll
        for (int i = 0; i < FBKV*DK/4/128; i++) {
            int e = tid + i*128;
            int r = e >> 4, c4 = (e & 15)*4;
            float4 k4 = *(const float4*)(Kg + (rowB + c0 + r)*ldkv + hc + c4);
            Ks[r][c4+0]=f2tf(k4.x); Ks[r][c4+1]=f2tf(k4.y);
            Ks[r][c4+2]=f2tf(k4.z); Ks[r][c4+3]=f2tf(k4.w);
            float4 v4 = *(const float4*)(Vg + (rowB + c0 + r)*ldkv + hc + c4);
            Vs[r][c4+0]=f2tf(v4.x); Vs[r][c4+1]=f2tf(v4.y);
            Vs[r][c4+2]=f2tf(v4.z); Vs[r][c4+3]=f2tf(v4.w);
        }
        __syncthreads();

        float s[8][4];
        #pragma unroll
        for (int nt=0; nt<8; nt++) { s[nt][0]=0.f; s[nt][1]=0.f; s[nt][2]=0.f; s[nt][3]=0.f; }
        #pragma unroll
        for (int kg = 0; kg < 8; kg++) {
            #pragma unroll
            for (int nt = 0; nt < 8; nt++) {
                uint32_t b0 = Ks[nt*8+gr][kg*8+t];
                uint32_t b1 = Ks[nt*8+gr][kg*8+t+4];
                MMA_TF32(s[nt], qa[kg][0],qa[kg][1],qa[kg][2],qa[kg][3], b0, b1);
            }
        }

        float mx0 = -INFINITY, mx1 = -INFINITY;
        #pragma unroll
        for (int nt=0; nt<8; nt++) {
            const int j0 = c0 + nt*8 + 2*t, j1 = j0 + 1;
            float v0=s[nt][0], v1=s[nt][1], v2=s[nt][2], v3=s[nt][3];
            if ((CAUSAL && j0 > r0l) || v0==0.f) v0 = -INFINITY;
            if ((CAUSAL && j1 > r0l) || v1==0.f) v1 = -INFINITY;
            if ((CAUSAL && j0 > r1l) || v2==0.f) v2 = -INFINITY;
            if ((CAUSAL && j1 > r1l) || v3==0.f) v3 = -INFINITY;
            s[nt][0]=v0; s[nt][1]=v1; s[nt][2]=v2; s[nt][3]=v3;
            mx0 = fmaxf(mx0, fmaxf(v0,v1));
            mx1 = fmaxf(mx1, fmaxf(v2,v3));
        }
        mx0 = fmaxf(mx0, __shfl_xor_sync(0xffffffffu, mx0, 1));
        mx0 = fmaxf(mx0, __shfl_xor_sync(0xffffffffu, mx0, 2));
        mx1 = fmaxf(mx1, __shfl_xor_sync(0xffffffffu, mx1, 1));
        mx1 = fmaxf(mx1, __shfl_xor_sync(0xffffffffu, mx1, 2));
        const float mn0 = fmaxf(m0, mx0), mn1 = fmaxf(m1, mx1);
        const float sc0 = __expf(m0 - mn0), sc1 = __expf(m1 - mn1);

        float ps0 = 0.f, ps1 = 0.f;
        #pragma unroll
        for (int nt=0; nt<8; nt++) {
            float p0 = __expf(s[nt][0] - mn0);
            float p1 = __expf(s[nt][1] - mn0);
            float p2 = __expf(s[nt][2] - mn1);
            float p3 = __expf(s[nt][3] - mn1);
            s[nt][0]=p0; s[nt][1]=p1; s[nt][2]=p2; s[nt][3]=p3;
            ps0 += p0 + p1; ps1 += p2 + p3;
        }
        ps0 += __shfl_xor_sync(0xffffffffu, ps0, 1);
        ps0 += __shfl_xor_sync(0xffffffffu, ps0, 2);
        ps1 += __shfl_xor_sync(0xffffffffu, ps1, 1);
        ps1 += __shfl_xor_sync(0xffffffffu, ps1, 2);
        l0 = l0*sc0 + ps0; l1 = l1*sc1 + ps1;
        m0 = mn0; m1 = mn1;
        #pragma unroll
        for (int d=0; d<8; d++) {
            o[d][0]*=sc0; o[d][1]*=sc0; o[d][2]*=sc1; o[d][3]*=sc1;
        }

        const int base = lane & ~3;
        #pragma unroll
        for (int kg=0; kg<8; kg++) {
            const int sA = base + (t>>1), sB = sA + 2;
            float xA0 = __shfl_sync(0xffffffffu, s[kg][0], sA);
            float xA1 = __shfl_sync(0xffffffffu, s[kg][1], sA);
            float xA2 = __shfl_sync(0xffffffffu, s[kg][2], sA);
            float xA3 = __shfl_sync(0xffffffffu, s[kg][3], sA);
            float xB0 = __shfl_sync(0xffffffffu, s[kg][0], sB);
            float xB1 = __shfl_sync(0xffffffffu, s[kg][1], sB);
            float xB2 = __shfl_sync(0xffffffffu, s[kg][2], sB);
            float xB3 = __shfl_sync(0xffffffffu, s[kg][3], sB);
            const uint32_t a0 = f2tf((t&1) ? xA1 : xA0);
            const uint32_t a1 = f2tf((t&1) ? xA3 : xA2);
            const uint32_t a2 = f2tf((t&1) ? xB1 : xB0);
            const uint32_t a3 = f2tf((t&1) ? xB3 : xB2);
            #pragma unroll
            for (int d=0; d<8; d++) {
                uint32_t b0 = Vs[kg*8+t  ][d*8+gr];
                uint32_t b1 = Vs[kg*8+t+4][d*8+gr];
                MMA_TF32(o[d], a0,a1,a2,a3, b0, b1);
            }
        }
        __syncthreads();
    }

    const float i0 = 1.f/l0, i1 = 1.f/l1;
    #pragma unroll
    for (int d=0; d<8; d++) {
        const int c = hc + d*8 + 2*t;
        *(float2*)(Og + (rowB + r0l)*DM + c) =
            make_float2(rtf(o[d][0]*i0), rtf(o[d][1]*i0));
        *(float2*)(Og + (rowB + r1l)*DM + c) =
            make_float2(rtf(o[d][2]*i1), rtf(o[d][3]*i1));
    }
}

// ---------------- LayerNorm (tf32-rounded output) ----------------
__global__ __launch_bounds__(256) void ln_k(const float* __restrict__ in,
                                            const float* __restrict__ al,
                                            const float* __restrict__ be,
                                            float* __restrict__ out)
{
    __shared__ float r1[8], r2[8];
    const long long base = (long long)blockIdx.x * DM;
    const int t = threadIdx.x;
    float2 v = *(const float2*)(in + base + t*2);
    float s = v.x + v.y;
    #pragma unroll
    for (int o=16;o;o>>=1) s += __shfl_xor_sync(0xffffffffu, s, o);
    if ((t&31)==0) r1[t>>5] = s;
    __syncthreads();
    float tot = 0.f;
    #pragma unroll
    for (int w=0;w<8;w++) tot += r1[w];
    const float mu = tot * (1.f/DM);

    const float d0 = v.x - mu, d1 = v.y - mu;
    float ss = d0*d0 + d1*d1;
    #pragma unroll
    for (int o=16;o;o>>=1) ss += __shfl_xor_sync(0xffffffffu, ss, o);
    if ((t&31)==0) r2[t>>5] = ss;
    __syncthreads();
    float tot2 = 0.f;
    #pragma unroll
    for (int w=0;w<8;w++) tot2 += r2[w];
    const float sd  = sqrtf(tot2 * (1.f/(DM-1)));
    const float inv = 1.f/(sd + EPSF);

    float a0 = al[t*2], a1 = al[t*2+1];
    float b0 = be[t*2], b1 = be[t*2+1];
    *(float2*)(out + base + t*2) =
        make_float2(rtf(a0*d0*inv + b0), rtf(a1*d1*inv + b1));
}

// ---------------- prep: round-copy into (possibly strided) dest ----------------
__global__ void rc_k(const float* __restrict__ src, float* __restrict__ dst,
                     int cols, int ldd, int n)
{
    int i = blockIdx.x*256 + threadIdx.x;
    if (i < n) {
        int r = i / cols, c = i % cols;
        dst[(long long)r*ldd + c] = rtf(src[i]);
    }
}

__global__ void copy_k(const float* __restrict__ a, float* __restrict__ b)
{
    const int i = blockIdx.x*blockDim.x + threadIdx.x;
    ((float4*)b)[i] = ((const float4*)a)[i];
}

// ---------------- launch ----------------
extern "C" void kernel_launch(void* const* d_in, const int* in_sizes, int n_in,
                              void* d_out, int out_size)
{
    const float* x    = (const float*)d_in[0];
    const float* mem  = (const float*)d_in[1];
    const float* ln1a = (const float*)d_in[2];
    const float* ln1b = (const float*)d_in[3];
    const float* ln2a = (const float*)d_in[4];
    const float* ln2b = (const float*)d_in[5];
    const float* ln3a = (const float*)d_in[6];
    const float* ln3b = (const float*)d_in[7];
    const float* wq1  = (const float*)d_in[8];
    const float* wk1  = (const float*)d_in[9];
    const float* wv1  = (const float*)d_in[10];
    const float* wo1  = (const float*)d_in[11];
    const float* bo1  = (const float*)d_in[12];
    const float* wq2  = (const float*)d_in[13];
    const float* wk2  = (const float*)d_in[14];
    const float* wv2  = (const float*)d_in[15];
    const float* wo2  = (const float*)d_in[16];
    const float* bo2  = (const float*)d_in[17];
    const float* fw1  = (const float*)d_in[18];
    const float* fb1  = (const float*)d_in[19];
    const float* fw2  = (const float*)d_in[20];
    const float* fb2  = (const float*)d_in[21];
    float* out = (float*)d_out;

    float *px,*px2,*pq,*pctx,*pqkv,*pkv,*pff,*pmem;
    float *pwqkv,*pwq2,*pwkv,*pwo1,*pwo2,*pfw1,*pfw2;
    cudaGetSymbolAddress((void**)&px,   g_x);
    cudaGetSymbolAddress((void**)&px2,  g_x2);
    cudaGetSymbolAddress((void**)&pq,   g_q);
    cudaGetSymbolAddress((void**)&pctx, g_ctx);
    cudaGetSymbolAddress((void**)&pqkv, g_qkv);
    cudaGetSymbolAddress((void**)&pkv,  g_kv);
    cudaGetSymbolAddress((void**)&pff,  g_ff);
    cudaGetSymbolAddress((void**)&pmem, g_mem);
    cudaGetSymbolAddress((void**)&pwqkv,g_wqkv);
    cudaGetSymbolAddress((void**)&pwq2, g_wq2);
    cudaGetSymbolAddress((void**)&pwkv, g_wkv);
    cudaGetSymbolAddress((void**)&pwo1, g_wo1);
    cudaGetSymbolAddress((void**)&pwo2, g_wo2);
    cudaGetSymbolAddress((void**)&pfw1, g_fw1);
    cudaGetSymbolAddress((void**)&pfw2, g_fw2);

    cudaFuncSetAttribute(tgemm<0>, cudaFuncAttributeMaxDynamicSharedMemorySize, GSMEM);
    cudaFuncSetAttribute(tgemm<2>, cudaFuncAttributeMaxDynamicSharedMemorySize, GSMEM);
    cudaFuncSetAttribute(tgemm<3>, cudaFuncAttributeMaxDynamicSharedMemorySize, GSMEM);

    const int nW  = DM*DM;
    const int gW  = (nW+255)/256;
    const int nF  = DM*DFF;
    const int gF  = (nF+255)/256;
    const int nM  = RT*DM;
    const int gM  = (nM+255)/256;

    // ---- prep: round weights (and mem) to tf32 values ----
    rc_k<<<gW, 256>>>(wq1, pwqkv + 0*DM,  DM, 3*DM, nW);
    rc_k<<<gW, 256>>>(wk1, pwqkv + 1*DM,  DM, 3*DM, nW);
    rc_k<<<gW, 256>>>(wv1, pwqkv + 2*DM,  DM, 3*DM, nW);
    rc_k<<<gW, 256>>>(wq2, pwq2,          DM, DM,   nW);
    rc_k<<<gW, 256>>>(wk2, pwkv + 0*DM,   DM, 2*DM, nW);
    rc_k<<<gW, 256>>>(wv2, pwkv + 1*DM,   DM, 2*DM, nW);
    rc_k<<<gW, 256>>>(wo1, pwo1,          DM, DM,   nW);
    rc_k<<<gW, 256>>>(wo2, pwo2,          DM, DM,   nW);
    rc_k<<<gF, 256>>>(fw1, pfw1,          DFF, DFF, nF);
    rc_k<<<gF, 256>>>(fw2, pfw2,          DM, DM,   nF);
    rc_k<<<gM, 256>>>(mem, pmem,          DM, DM,   nM);

    copy_k<<<2048, 256>>>(x, px);

    const dim3 gQKV(12, 32), gP(4, 32), gKV(8, 32), gFF1(16, 32);
    const dim3 gFlash(SQ/FBQ, NB*NH);

    // ---- self attention ----
    ln_k<<<RT, 256>>>(px, ln1a, ln1b, px2);
    tgemm<0><<<gQKV, 256, GSMEM>>>(px2, pwqkv, pqkv, nullptr, nullptr, DM, DM, 3*DM, 3*DM);
    flash_k<true><<<gFlash, 128>>>(pqkv, pqkv + DM, pqkv + 2*DM, pctx, 3*DM, 3*DM);
    tgemm<3><<<gP, 256, GSMEM>>>(pctx, pwo1, px, bo1, px, DM, DM, DM, DM);

    // ---- cross attention ----
    ln_k<<<RT, 256>>>(px, ln2a, ln2b, px2);
    tgemm<0><<<gP, 256, GSMEM>>>(px2, pwq2, pq, nullptr, nullptr, DM, DM, DM, DM);
    tgemm<0><<<gKV, 256, GSMEM>>>(pmem, pwkv, pkv, nullptr, nullptr, DM, DM, 2*DM, 2*DM);
    flash_k<false><<<gFlash, 128>>>(pq, pkv, pkv + DM, pctx, DM, 2*DM);
    tgemm<3><<<gP, 256, GSMEM>>>(pctx, pwo2, px, bo2, px, DM, DM, DM, DM);

    // ---- feed forward ----
    ln_k<<<RT, 256>>>(px, ln3a, ln3b, px2);
    tgemm<2><<<gFF1, 256, GSMEM>>>(px2, pfw1, pff, fb1, nullptr, DM, DM, DFF, DFF);
    tgemm<3><<<gP, 256, GSMEM>>>(pff, pfw2, out, fb2, px, DFF, DFF, DM, DM);
}

// round 8
// speedup vs baseline: 7.5226x; 1.9492x over previous
#include <cuda_runtime.h>
#include <cuda_fp16.h>
#include <math.h>
#include <stdint.h>

#define DM   512
#define NH   8
#define DK   64
#define DFF  2048
#define NB   2
#define SQ   2048
#define RT   (NB*SQ)
#define EPSF 1e-6f

// ---------------- scratch ----------------
__device__ float  g_x   [RT*DM];          // fp32 residual stream
__device__ __half g_x2h [RT*DM];          // LN outputs (GEMM A)
__device__ __half g_qkvh[RT*3*DM];
__device__ __half g_qh  [RT*DM];
__device__ __half g_kvh [RT*2*DM];
__device__ __half g_ctxh[RT*DM];
__device__ __half g_ffh [RT*DFF];
__device__ __half g_memh[RT*DM];
// transposed ([N,K]) fp16 weights
__device__ __half g_wqkvt[3*DM*DM];
__device__ __half g_wq2t [DM*DM];
__device__ __half g_wkvt [2*DM*DM];
__device__ __half g_wo1t [DM*DM];
__device__ __half g_wo2t [DM*DM];
__device__ __half g_fw1t [DFF*DM];
__device__ __half g_fw2t [DM*DFF];

__device__ __forceinline__ uint32_t s2u(const void* p) {
    uint32_t a;
    asm("{ .reg .u64 t; cvta.to.shared.u64 t, %1; cvt.u32.u64 %0, t; }" : "=r"(a) : "l"(p));
    return a;
}
__device__ __forceinline__ uint32_t packh2(float a, float b) {
    __half2 h = __floats2half2_rn(a, b);
    return *(uint32_t*)&h;
}
__device__ __forceinline__ void cp16(uint32_t dst, const void* src) {
    asm volatile("cp.async.ca.shared.global [%0], [%1], 16;" :: "r"(dst), "l"(src));
}
#define CP_COMMIT asm volatile("cp.async.commit_group;")

#define MMA_F16(acc, a0,a1,a2,a3, b0,b1) \
    asm volatile("mma.sync.aligned.m16n8k16.row.col.f32.f16.f16.f32 " \
                 "{%0,%1,%2,%3}, {%4,%5,%6,%7}, {%8,%9}, {%0,%1,%2,%3};" \
                 : "+f"(acc[0]), "+f"(acc[1]), "+f"(acc[2]), "+f"(acc[3]) \
                 : "r"(a0), "r"(a1), "r"(a2), "r"(a3), "r"(b0), "r"(b1))

#define LDSM4(r0,r1,r2,r3, addr) \
    asm volatile("ldmatrix.sync.aligned.m8n8.x4.shared.b16 {%0,%1,%2,%3}, [%4];" \
                 : "=r"(r0), "=r"(r1), "=r"(r2), "=r"(r3) : "r"(addr))
#define LDSM4T(r0,r1,r2,r3, addr) \
    asm volatile("ldmatrix.sync.aligned.m8n8.x4.trans.shared.b16 {%0,%1,%2,%3}, [%4];" \
                 : "=r"(r0), "=r"(r1), "=r"(r2), "=r"(r3) : "r"(addr))

// ---------------- fp16 ldmatrix GEMM ----------------
// C[4096, Nout] = A[4096, K](f16) * Bt[Nout, K](f16)^T
// 128x128 tiles, BK=64 halves (128B SW128 rows), 3-stage cp.async, 256 thr (2x4 warps, 64x32).
// FUSE: 0=plain (f16 out), 2=bias+relu (f16 out), 3=bias+residual (f32 out)
#define STB 32768                   // bytes per stage (A 16K + B 16K)
#define GSMEM (3*STB)

template<int FUSE>
__global__ void __launch_bounds__(256, 2)
hgemm(const __half* __restrict__ A, const __half* __restrict__ Bt, void* __restrict__ Cv,
      const float* __restrict__ bias, const float* __restrict__ res, int K, int ldc)
{
    extern __shared__ char smem[];
    const uint32_t sb = s2u(smem);
    const int tid = threadIdx.x, lane = tid & 31, wid = tid >> 5;
    const int wm = wid >> 2, wn = wid & 3;
    const int row0 = blockIdx.y * 128, col0 = blockIdx.x * 128;

    auto loadA = [&](int s, int it) {
        const __half* Ag = A + (long long)row0 * K + it * 64;
        const uint32_t d0 = sb + s * STB;
        #pragma unroll
        for (int i = 0; i < 4; i++) {
            const int e = tid + i * 256, r = e >> 3, c = e & 7;
            cp16(d0 + r * 128 + ((c ^ (r & 7)) << 4), Ag + (long long)r * K + c * 8);
        }
    };
    auto loadB = [&](int s, int it) {
        const __half* Bg = Bt + (long long)col0 * K + it * 64;
        const uint32_t d0 = sb + s * STB + 16384;
        #pragma unroll
        for (int i = 0; i < 4; i++) {
            const int e = tid + i * 256, r = e >> 3, c = e & 7;
            cp16(d0 + r * 128 + ((c ^ (r & 7)) << 4), Bg + (long long)r * K + c * 8);
        }
    };

    float acc[4][4][4];
    #pragma unroll
    for (int i = 0; i < 4; i++)
        #pragma unroll
        for (int j = 0; j < 4; j++)
            #pragma unroll
            for (int q = 0; q < 4; q++) acc[i][j][q] = 0.f;

    const int NIT = K / 64;
    loadA(0, 0); loadB(0, 0); CP_COMMIT;
    loadA(1, 1); loadB(1, 1); CP_COMMIT;

    for (int it = 0; it < NIT; it++) {
        asm volatile("cp.async.wait_group 1;");
        __syncthreads();
        const int j = it + 2;
        if (j < NIT) { loadA(j % 3, j); loadB(j % 3, j); }
        CP_COMMIT;

        const uint32_t sa = sb + (it % 3) * STB;
        const uint32_t sB = sa + 16384;
        #pragma unroll
        for (int kg = 0; kg < 4; kg++) {
            uint32_t af[4][4], bf[4][2];
            #pragma unroll
            for (int mt = 0; mt < 4; mt++) {
                const int r = wm * 64 + mt * 16 + (lane & 7) + ((lane >> 3) & 1) * 8;
                const int ch = kg * 2 + (lane >> 4);
                LDSM4(af[mt][0], af[mt][1], af[mt][2], af[mt][3],
                      sa + r * 128 + ((ch ^ (r & 7)) << 4));
            }
            #pragma unroll
            for (int p = 0; p < 2; p++) {
                const int r = wn * 32 + p * 16 + (lane & 7) + ((lane >> 4) & 1) * 8;
                const int ch = kg * 2 + ((lane >> 3) & 1);
                uint32_t b0, b1, b2, b3;
                LDSM4(b0, b1, b2, b3, sB + r * 128 + ((ch ^ (r & 7)) << 4));
                bf[2*p][0] = b0; bf[2*p][1] = b1; bf[2*p+1][0] = b2; bf[2*p+1][1] = b3;
            }
            #pragma unroll
            for (int mt = 0; mt < 4; mt++)
                #pragma unroll
                for (int nt = 0; nt < 4; nt++)
                    MMA_F16(acc[mt][nt], af[mt][0], af[mt][1], af[mt][2], af[mt][3],
                            bf[nt][0], bf[nt][1]);
        }
    }

    // epilogue
    #pragma unroll
    for (int mt = 0; mt < 4; mt++) {
        #pragma unroll
        for (int nt = 0; nt < 4; nt++) {
            const int r = row0 + wm * 64 + mt * 16 + (lane >> 2);
            const int c = col0 + wn * 32 + nt * 8 + 2 * (lane & 3);
            float v0 = acc[mt][nt][0], v1 = acc[mt][nt][1];
            float v2 = acc[mt][nt][2], v3 = acc[mt][nt][3];
            if (FUSE >= 2) {
                const float b0 = bias[c], b1 = bias[c + 1];
                v0 += b0; v1 += b1; v2 += b0; v3 += b1;
            }
            if (FUSE == 2) {
                v0 = fmaxf(v0, 0.f); v1 = fmaxf(v1, 0.f);
                v2 = fmaxf(v2, 0.f); v3 = fmaxf(v3, 0.f);
            }
            if (FUSE == 3) {
                float* C = (float*)Cv;
                const float2 r0 = *(const float2*)(res + (long long)r * ldc + c);
                const float2 r1 = *(const float2*)(res + (long long)(r + 8) * ldc + c);
                *(float2*)(C + (long long)r * ldc + c)       = make_float2(v0 + r0.x, v1 + r0.y);
                *(float2*)(C + (long long)(r + 8) * ldc + c) = make_float2(v2 + r1.x, v3 + r1.y);
            } else {
                __half* C = (__half*)Cv;
                *(__half2*)(C + (long long)r * ldc + c)       = __floats2half2_rn(v0, v1);
                *(__half2*)(C + (long long)(r + 8) * ldc + c) = __floats2half2_rn(v2, v3);
            }
        }
    }
}

// ---------------- fused flash attention (fp16 MMA + ldmatrix, online softmax) ----------------
// s = (q.k)/8 (scale applied post-mma, exact) ; causal j>q -> -inf ; s==0 -> -inf ; softmax ; P.V
#define FBQ  64
#define FBKV 64

template<bool CAUSAL>
__global__ void __launch_bounds__(128, 2)
flash_k(const __half* __restrict__ Qg, const __half* __restrict__ Kg,
        const __half* __restrict__ Vg, __half* __restrict__ Og, int ldq, int ldkv)
{
    __shared__ __align__(128) char sm[16384];
    const uint32_t sK = s2u(sm), sV = sK + 8192;

    const int bz = blockIdx.y;
    const int b = bz / NH, h = bz % NH;
    const int qt = blockIdx.x;
    const int tid = threadIdx.x, lane = tid & 31, w = tid >> 5;
    const int t = lane & 3;
    const int q0 = qt * FBQ;
    const long long rowB = (long long)b * SQ;
    const int hc = h * DK;

    // ---- Q tile -> smem (swizzled) -> A-frags ----
    #pragma unroll
    for (int i = 0; i < 4; i++) {
        const int e = tid + i * 128, r = e >> 3, c = e & 7;
        cp16(sK + r * 128 + ((c ^ (r & 7)) << 4), Qg + (rowB + q0 + r) * ldq + hc + c * 8);
    }
    CP_COMMIT;
    asm volatile("cp.async.wait_group 0;");
    __syncthreads();
    uint32_t qa[4][4];
    #pragma unroll
    for (int kg = 0; kg < 4; kg++) {
        const int r = w * 16 + (lane & 7) + ((lane >> 3) & 1) * 8;
        const int ch = kg * 2 + (lane >> 4);
        LDSM4(qa[kg][0], qa[kg][1], qa[kg][2], qa[kg][3],
              sK + r * 128 + ((ch ^ (r & 7)) << 4));
    }
    __syncthreads();

    float o[8][4];
    #pragma unroll
    for (int d = 0; d < 8; d++) { o[d][0]=0.f; o[d][1]=0.f; o[d][2]=0.f; o[d][3]=0.f; }
    float m0 = -INFINITY, m1 = -INFINITY, l0 = 0.f, l1 = 0.f;
    const int r0l = q0 + w * 16 + (lane >> 2);
    const int r1l = r0l + 8;

    const int nch = CAUSAL ? (qt + 1) : (SQ / FBKV);
    for (int chk = 0; chk < nch; chk++) {
        const int c0 = chk * FBKV;
        #pragma unroll
        for (int i = 0; i < 4; i++) {
            const int e = tid + i * 128, r = e >> 3, c = e & 7;
            cp16(sK + r * 128 + ((c ^ (r & 7)) << 4), Kg + (rowB + c0 + r) * ldkv + hc + c * 8);
            cp16(sV + r * 128 + ((c ^ (r & 7)) << 4), Vg + (rowB + c0 + r) * ldkv + hc + c * 8);
        }
        CP_COMMIT;
        asm volatile("cp.async.wait_group 0;");
        __syncthreads();

        // ---- S = Q.K^T ----
        float s[8][4];
        #pragma unroll
        for (int nt = 0; nt < 8; nt++) { s[nt][0]=0.f; s[nt][1]=0.f; s[nt][2]=0.f; s[nt][3]=0.f; }
        #pragma unroll
        for (int kg = 0; kg < 4; kg++) {
            #pragma unroll
            for (int p = 0; p < 4; p++) {
                const int r = p * 16 + (lane & 7) + ((lane >> 4) & 1) * 8;
                const int ch = kg * 2 + ((lane >> 3) & 1);
                uint32_t b0, b1, b2, b3;
                LDSM4(b0, b1, b2, b3, sK + r * 128 + ((ch ^ (r & 7)) << 4));
                MMA_F16(s[2*p],   qa[kg][0], qa[kg][1], qa[kg][2], qa[kg][3], b0, b1);
                MMA_F16(s[2*p+1], qa[kg][0], qa[kg][1], qa[kg][2], qa[kg][3], b2, b3);
            }
        }

        // ---- scale + mask + online softmax ----
        float mx0 = -INFINITY, mx1 = -INFINITY;
        #pragma unroll
        for (int nt = 0; nt < 8; nt++) {
            const int j0 = c0 + nt * 8 + 2 * t, j1 = j0 + 1;
            float v0 = s[nt][0] * 0.125f, v1 = s[nt][1] * 0.125f;
            float v2 = s[nt][2] * 0.125f, v3 = s[nt][3] * 0.125f;
            if ((CAUSAL && j0 > r0l) || v0 == 0.f) v0 = -INFINITY;
            if ((CAUSAL && j1 > r0l) || v1 == 0.f) v1 = -INFINITY;
            if ((CAUSAL && j0 > r1l) || v2 == 0.f) v2 = -INFINITY;
            if ((CAUSAL && j1 > r1l) || v3 == 0.f) v3 = -INFINITY;
            s[nt][0] = v0; s[nt][1] = v1; s[nt][2] = v2; s[nt][3] = v3;
            mx0 = fmaxf(mx0, fmaxf(v0, v1));
            mx1 = fmaxf(mx1, fmaxf(v2, v3));
        }
        mx0 = fmaxf(mx0, __shfl_xor_sync(0xffffffffu, mx0, 1));
        mx0 = fmaxf(mx0, __shfl_xor_sync(0xffffffffu, mx0, 2));
        mx1 = fmaxf(mx1, __shfl_xor_sync(0xffffffffu, mx1, 1));
        mx1 = fmaxf(mx1, __shfl_xor_sync(0xffffffffu, mx1, 2));
        const float mn0 = fmaxf(m0, mx0), mn1 = fmaxf(m1, mx1);
        const float sc0 = __expf(m0 - mn0), sc1 = __expf(m1 - mn1);

        float ps0 = 0.f, ps1 = 0.f;
        #pragma unroll
        for (int nt = 0; nt < 8; nt++) {
            const float p0 = __expf(s[nt][0] - mn0);
            const float p1 = __expf(s[nt][1] - mn0);
            const float p2 = __expf(s[nt][2] - mn1);
            const float p3 = __expf(s[nt][3] - mn1);
            s[nt][0] = p0; s[nt][1] = p1; s[nt][2] = p2; s[nt][3] = p3;
            ps0 += p0 + p1; ps1 += p2 + p3;
        }
        ps0 += __shfl_xor_sync(0xffffffffu, ps0, 1);
        ps0 += __shfl_xor_sync(0xffffffffu, ps0, 2);
        ps1 += __shfl_xor_sync(0xffffffffu, ps1, 1);
        ps1 += __shfl_xor_sync(0xffffffffu, ps1, 2);
        l0 = l0 * sc0 + ps0; l1 = l1 * sc1 + ps1;
        m0 = mn0; m1 = mn1;
        #pragma unroll
        for (int d = 0; d < 8; d++) {
            o[d][0] *= sc0; o[d][1] *= sc0; o[d][2] *= sc1; o[d][3] *= sc1;
        }

        // ---- O += P.V : fp16 A-frag = direct pack of S C-frags ----
        #pragma unroll
        for (int kg = 0; kg < 4; kg++) {
            const uint32_t a0 = packh2(s[2*kg][0],   s[2*kg][1]);
            const uint32_t a1 = packh2(s[2*kg][2],   s[2*kg][3]);
            const uint32_t a2 = packh2(s[2*kg+1][0], s[2*kg+1][1]);
            const uint32_t a3 = packh2(s[2*kg+1][2], s[2*kg+1][3]);
            #pragma unroll
            for (int p = 0; p < 4; p++) {
                const int r = kg * 16 + (lane & 7) + ((lane >> 3) & 1) * 8;
                const int ch = p * 2 + (lane >> 4);
                uint32_t v0, v1, v2, v3;
                LDSM4T(v0, v1, v2, v3, sV + r * 128 + ((ch ^ (r & 7)) << 4));
                MMA_F16(o[2*p],   a0, a1, a2, a3, v0, v1);
                MMA_F16(o[2*p+1], a0, a1, a2, a3, v2, v3);
            }
        }
        __syncthreads();
    }

    const float i0 = 1.f / l0, i1 = 1.f / l1;
    #pragma unroll
    for (int d = 0; d < 8; d++) {
        const int c = hc + d * 8 + 2 * t;
        *(__half2*)(Og + (rowB + r0l) * DM + c) = __floats2half2_rn(o[d][0] * i0, o[d][1] * i0);
        *(__half2*)(Og + (rowB + r1l) * DM + c) = __floats2half2_rn(o[d][2] * i1, o[d][3] * i1);
    }
}

// ---------------- LayerNorm (fp32 in, fp16 out) ----------------
__global__ __launch_bounds__(256) void ln_k(const float* __restrict__ in,
                                            const float* __restrict__ al,
                                            const float* __restrict__ be,
                                            __half* __restrict__ out)
{
    __shared__ float r1[8], r2[8];
    const long long base = (long long)blockIdx.x * DM;
    const int t = threadIdx.x;
    float2 v = *(const float2*)(in + base + t*2);
    float s = v.x + v.y;
    #pragma unroll
    for (int o=16;o;o>>=1) s += __shfl_xor_sync(0xffffffffu, s, o);
    if ((t&31)==0) r1[t>>5] = s;
    __syncthreads();
    float tot = 0.f;
    #pragma unroll
    for (int w=0;w<8;w++) tot += r1[w];
    const float mu = tot * (1.f/DM);

    const float d0 = v.x - mu, d1 = v.y - mu;
    float ss = d0*d0 + d1*d1;
    #pragma unroll
    for (int o=16;o;o>>=1) ss += __shfl_xor_sync(0xffffffffu, ss, o);
    if ((t&31)==0) r2[t>>5] = ss;
    __syncthreads();
    float tot2 = 0.f;
    #pragma unroll
    for (int w=0;w<8;w++) tot2 += r2[w];
    const float sd  = sqrtf(tot2 * (1.f/(DM-1)));
    const float inv = 1.f/(sd + EPSF);

    const float a0 = al[t*2], a1 = al[t*2+1];
    const float b0 = be[t*2], b1 = be[t*2+1];
    *(__half2*)(out + base + t*2) = __floats2half2_rn(a0*d0*inv + b0, a1*d1*inv + b1);
}

// ---------------- prep kernels ----------------
// transpose + fp16: src fp32 [Kd][Nd] -> dst fp16 [Nd][Kd]
__global__ __launch_bounds__(256) void tr_k(const float* __restrict__ src,
                                            __half* __restrict__ dst, int Kd, int Nd)
{
    __shared__ float t[32][33];
    const int nb = blockIdx.x*32, kb = blockIdx.y*32;
    const int tx = threadIdx.x & 31, ty = threadIdx.x >> 5;
    #pragma unroll
    for (int i = 0; i < 32; i += 8)
        t[ty+i][tx] = src[(long long)(kb+ty+i)*Nd + nb+tx];
    __syncthreads();
    #pragma unroll
    for (int i = 0; i < 32; i += 8)
        dst[(long long)(nb+ty+i)*Kd + kb+tx] = __float2half(t[tx][ty+i]);
}

__global__ void rc_k(const float* __restrict__ src, __half* __restrict__ dst, int n)
{
    const int i = blockIdx.x*256 + threadIdx.x;
    if (i < n) dst[i] = __float2half(src[i]);
}

__global__ void copy_k(const float* __restrict__ a, float* __restrict__ b)
{
    const int i = blockIdx.x*blockDim.x + threadIdx.x;
    ((float4*)b)[i] = ((const float4*)a)[i];
}

// ---------------- launch ----------------
extern "C" void kernel_launch(void* const* d_in, const int* in_sizes, int n_in,
                              void* d_out, int out_size)
{
    const float* x    = (const float*)d_in[0];
    const float* mem  = (const float*)d_in[1];
    const float* ln1a = (const float*)d_in[2];
    const float* ln1b = (const float*)d_in[3];
    const float* ln2a = (const float*)d_in[4];
    const float* ln2b = (const float*)d_in[5];
    const float* ln3a = (const float*)d_in[6];
    const float* ln3b = (const float*)d_in[7];
    const float* wq1  = (const float*)d_in[8];
    const float* wk1  = (const float*)d_in[9];
    const float* wv1  = (const float*)d_in[10];
    const float* wo1  = (const float*)d_in[11];
    const float* bo1  = (const float*)d_in[12];
    const float* wq2  = (const float*)d_in[13];
    const float* wk2  = (const float*)d_in[14];
    const float* wv2  = (const float*)d_in[15];
    const float* wo2  = (const float*)d_in[16];
    const float* bo2  = (const float*)d_in[17];
    const float* fw1  = (const float*)d_in[18];
    const float* fb1  = (const float*)d_in[19];
    const float* fw2  = (const float*)d_in[20];
    const float* fb2  = (const float*)d_in[21];
    float* out = (float*)d_out;

    float* px;
    __half *px2h,*pqkvh,*pqh,*pkvh,*pctxh,*pffh,*pmemh;
    __half *pwqkvt,*pwq2t,*pwkvt,*pwo1t,*pwo2t,*pfw1t,*pfw2t;
    cudaGetSymbolAddress((void**)&px,    g_x);
    cudaGetSymbolAddress((void**)&px2h,  g_x2h);
    cudaGetSymbolAddress((void**)&pqkvh, g_qkvh);
    cudaGetSymbolAddress((void**)&pqh,   g_qh);
    cudaGetSymbolAddress((void**)&pkvh,  g_kvh);
    cudaGetSymbolAddress((void**)&pctxh, g_ctxh);
    cudaGetSymbolAddress((void**)&pffh,  g_ffh);
    cudaGetSymbolAddress((void**)&pmemh, g_memh);
    cudaGetSymbolAddress((void**)&pwqkvt,g_wqkvt);
    cudaGetSymbolAddress((void**)&pwq2t, g_wq2t);
    cudaGetSymbolAddress((void**)&pwkvt, g_wkvt);
    cudaGetSymbolAddress((void**)&pwo1t, g_wo1t);
    cudaGetSymbolAddress((void**)&pwo2t, g_wo2t);
    cudaGetSymbolAddress((void**)&pfw1t, g_fw1t);
    cudaGetSymbolAddress((void**)&pfw2t, g_fw2t);

    cudaFuncSetAttribute(hgemm<0>, cudaFuncAttributeMaxDynamicSharedMemorySize, GSMEM);
    cudaFuncSetAttribute(hgemm<2>, cudaFuncAttributeMaxDynamicSharedMemorySize, GSMEM);
    cudaFuncSetAttribute(hgemm<3>, cudaFuncAttributeMaxDynamicSharedMemorySize, GSMEM);

    // ---- prep: transpose+convert weights to [N,K] fp16; convert mem; copy x ----
    const dim3 tb(256);
    const dim3 gT512(16, 16);
    tr_k<<<gT512, tb>>>(wq1, pwqkvt + 0*DM*DM, DM, DM);
    tr_k<<<gT512, tb>>>(wk1, pwqkvt + 1*DM*DM, DM, DM);
    tr_k<<<gT512, tb>>>(wv1, pwqkvt + 2*DM*DM, DM, DM);
    tr_k<<<gT512, tb>>>(wq2, pwq2t, DM, DM);
    tr_k<<<gT512, tb>>>(wk2, pwkvt + 0*DM*DM, DM, DM);
    tr_k<<<gT512, tb>>>(wv2, pwkvt + 1*DM*DM, DM, DM);
    tr_k<<<gT512, tb>>>(wo1, pwo1t, DM, DM);
    tr_k<<<gT512, tb>>>(wo2, pwo2t, DM, DM);
    tr_k<<<dim3(DFF/32, DM/32), tb>>>(fw1, pfw1t, DM, DFF);
    tr_k<<<dim3(DM/32, DFF/32), tb>>>(fw2, pfw2t, DFF, DM);
    rc_k<<<(RT*DM+255)/256, 256>>>(mem, pmemh, RT*DM);
    copy_k<<<2048, 256>>>(x, px);

    const dim3 gQKV(12, 32), gP(4, 32), gKV(8, 32), gFF1(16, 32);
    const dim3 gFlash(SQ/FBQ, NB*NH);

    // ---- self attention ----
    ln_k<<<RT, 256>>>(px, ln1a, ln1b, px2h);
    hgemm<0><<<gQKV, 256, GSMEM>>>(px2h, pwqkvt, pqkvh, nullptr, nullptr, DM, 3*DM);
    flash_k<true><<<gFlash, 128>>>(pqkvh, pqkvh + DM, pqkvh + 2*DM, pctxh, 3*DM, 3*DM);
    hgemm<3><<<gP, 256, GSMEM>>>(pctxh, pwo1t, px, bo1, px, DM, DM);

    // ---- cross attention ----
    ln_k<<<RT, 256>>>(px, ln2a, ln2b, px2h);
    hgemm<0><<<gP, 256, GSMEM>>>(px2h, pwq2t, pqh, nullptr, nullptr, DM, DM);
    hgemm<0><<<gKV, 256, GSMEM>>>(pmemh, pwkvt, pkvh, nullptr, nullptr, DM, 2*DM);
    flash_k<false><<<gFlash, 128>>>(pqh, pkvh, pkvh + DM, pctxh, DM, 2*DM);
    hgemm<3><<<gP, 256, GSMEM>>>(pctxh, pwo2t, px, bo2, px, DM, DM);

    // ---- feed forward ----
    ln_k<<<RT, 256>>>(px, ln3a, ln3b, px2h);
    hgemm<2><<<gFF1, 256, GSMEM>>>(px2h, pfw1t, pffh, fb1, nullptr, DM, DFF);
    hgemm<3><<<gP, 256, GSMEM>>>(pffh, pfw2t, out, fb2, px, DFF, DM);
}

// round 9
// speedup vs baseline: 7.9633x; 1.0586x over previous
#include <cuda_runtime.h>
#include <cuda_fp16.h>
#include <math.h>
#include <stdint.h>

#define DM   512
#define NH   8
#define DK   64
#define DFF  2048
#define NB   2
#define SQ   2048
#define RT   (NB*SQ)
#define EPSF 1e-6f

// ---------------- scratch ----------------
__device__ float  g_x   [RT*DM];          // fp32 residual stream
__device__ __half g_x2h [RT*DM];          // LN outputs (GEMM A)
__device__ __half g_qkvh[RT*3*DM];
__device__ __half g_qh  [RT*DM];
__device__ __half g_kvh [RT*2*DM];
__device__ __half g_ctxh[RT*DM];
__device__ __half g_ffh [RT*DFF];
__device__ __half g_memh[RT*DM];
// transposed ([N,K]) fp16 weights
__device__ __half g_wqkvt[3*DM*DM];
__device__ __half g_wq2t [DM*DM];
__device__ __half g_wkvt [2*DM*DM];
__device__ __half g_wo1t [DM*DM];
__device__ __half g_wo2t [DM*DM];
__device__ __half g_fw1t [DFF*DM];
__device__ __half g_fw2t [DM*DFF];

__device__ __forceinline__ uint32_t s2u(const void* p) {
    uint32_t a;
    asm("{ .reg .u64 t; cvta.to.shared.u64 t, %1; cvt.u32.u64 %0, t; }" : "=r"(a) : "l"(p));
    return a;
}
__device__ __forceinline__ uint32_t packh2(float a, float b) {
    __half2 h = __floats2half2_rn(a, b);
    return *(uint32_t*)&h;
}
__device__ __forceinline__ void cp16(uint32_t dst, const void* src) {
    asm volatile("cp.async.ca.shared.global [%0], [%1], 16;" :: "r"(dst), "l"(src));
}
#define CP_COMMIT asm volatile("cp.async.commit_group;")

#define MMA_F16(acc, a0,a1,a2,a3, b0,b1) \
    asm volatile("mma.sync.aligned.m16n8k16.row.col.f32.f16.f16.f32 " \
                 "{%0,%1,%2,%3}, {%4,%5,%6,%7}, {%8,%9}, {%0,%1,%2,%3};" \
                 : "+f"(acc[0]), "+f"(acc[1]), "+f"(acc[2]), "+f"(acc[3]) \
                 : "r"(a0), "r"(a1), "r"(a2), "r"(a3), "r"(b0), "r"(b1))

#define LDSM4(r0,r1,r2,r3, addr) \
    asm volatile("ldmatrix.sync.aligned.m8n8.x4.shared.b16 {%0,%1,%2,%3}, [%4];" \
                 : "=r"(r0), "=r"(r1), "=r"(r2), "=r"(r3) : "r"(addr))
#define LDSM4T(r0,r1,r2,r3, addr) \
    asm volatile("ldmatrix.sync.aligned.m8n8.x4.trans.shared.b16 {%0,%1,%2,%3}, [%4];" \
                 : "=r"(r0), "=r"(r1), "=r"(r2), "=r"(r3) : "r"(addr))

// ---------------- fp16 ldmatrix GEMM ----------------
// C[4096, Nout] = A[4096, K](f16) * Bt[Nout, K](f16)^T
// 128x128 tiles, BK=64 halves (128B SW128 rows), 3-stage cp.async, 256 thr (2x4 warps, 64x32).
// FUSE: 0=plain (f16 out), 2=bias+relu (f16 out), 3=bias+residual (f32 out)
#define STB 32768                   // bytes per stage (A 16K + B 16K)
#define GSMEM (3*STB)

template<int FUSE>
__global__ void __launch_bounds__(256, 2)
hgemm(const __half* __restrict__ A, const __half* __restrict__ Bt, void* __restrict__ Cv,
      const float* __restrict__ bias, const float* __restrict__ res, int K, int ldc)
{
    extern __shared__ char smem[];
    const uint32_t sb = s2u(smem);
    const int tid = threadIdx.x, lane = tid & 31, wid = tid >> 5;
    const int wm = wid >> 2, wn = wid & 3;
    const int row0 = blockIdx.y * 128, col0 = blockIdx.x * 128;

    auto loadA = [&](int s, int it) {
        const __half* Ag = A + (long long)row0 * K + it * 64;
        const uint32_t d0 = sb + s * STB;
        #pragma unroll
        for (int i = 0; i < 4; i++) {
            const int e = tid + i * 256, r = e >> 3, c = e & 7;
            cp16(d0 + r * 128 + ((c ^ (r & 7)) << 4), Ag + (long long)r * K + c * 8);
        }
    };
    auto loadB = [&](int s, int it) {
        const __half* Bg = Bt + (long long)col0 * K + it * 64;
        const uint32_t d0 = sb + s * STB + 16384;
        #pragma unroll
        for (int i = 0; i < 4; i++) {
            const int e = tid + i * 256, r = e >> 3, c = e & 7;
            cp16(d0 + r * 128 + ((c ^ (r & 7)) << 4), Bg + (long long)r * K + c * 8);
        }
    };

    float acc[4][4][4];
    #pragma unroll
    for (int i = 0; i < 4; i++)
        #pragma unroll
        for (int j = 0; j < 4; j++)
            #pragma unroll
            for (int q = 0; q < 4; q++) acc[i][j][q] = 0.f;

    const int NIT = K / 64;
    loadA(0, 0); loadB(0, 0); CP_COMMIT;
    loadA(1, 1); loadB(1, 1); CP_COMMIT;

    for (int it = 0; it < NIT; it++) {
        asm volatile("cp.async.wait_group 1;");
        __syncthreads();
        const int j = it + 2;
        if (j < NIT) { loadA(j % 3, j); loadB(j % 3, j); }
        CP_COMMIT;

        const uint32_t sa = sb + (it % 3) * STB;
        const uint32_t sB = sa + 16384;
        #pragma unroll
        for (int kg = 0; kg < 4; kg++) {
            uint32_t af[4][4], bf[4][2];
            #pragma unroll
            for (int mt = 0; mt < 4; mt++) {
                const int r = wm * 64 + mt * 16 + (lane & 7) + ((lane >> 3) & 1) * 8;
                const int ch = kg * 2 + (lane >> 4);
                LDSM4(af[mt][0], af[mt][1], af[mt][2], af[mt][3],
                      sa + r * 128 + ((ch ^ (r & 7)) << 4));
            }
            #pragma unroll
            for (int p = 0; p < 2; p++) {
                const int r = wn * 32 + p * 16 + (lane & 7) + ((lane >> 4) & 1) * 8;
                const int ch = kg * 2 + ((lane >> 3) & 1);
                uint32_t b0, b1, b2, b3;
                LDSM4(b0, b1, b2, b3, sB + r * 128 + ((ch ^ (r & 7)) << 4));
                bf[2*p][0] = b0; bf[2*p][1] = b1; bf[2*p+1][0] = b2; bf[2*p+1][1] = b3;
            }
            #pragma unroll
            for (int mt = 0; mt < 4; mt++)
                #pragma unroll
                for (int nt = 0; nt < 4; nt++)
                    MMA_F16(acc[mt][nt], af[mt][0], af[mt][1], af[mt][2], af[mt][3],
                            bf[nt][0], bf[nt][1]);
        }
    }

    // epilogue
    #pragma unroll
    for (int mt = 0; mt < 4; mt++) {
        #pragma unroll
        for (int nt = 0; nt < 4; nt++) {
            const int r = row0 + wm * 64 + mt * 16 + (lane >> 2);
            const int c = col0 + wn * 32 + nt * 8 + 2 * (lane & 3);
            float v0 = acc[mt][nt][0], v1 = acc[mt][nt][1];
            float v2 = acc[mt][nt][2], v3 = acc[mt][nt][3];
            if (FUSE >= 2) {
                const float b0 = bias[c], b1 = bias[c + 1];
                v0 += b0; v1 += b1; v2 += b0; v3 += b1;
            }
            if (FUSE == 2) {
                v0 = fmaxf(v0, 0.f); v1 = fmaxf(v1, 0.f);
                v2 = fmaxf(v2, 0.f); v3 = fmaxf(v3, 0.f);
            }
            if (FUSE == 3) {
                float* C = (float*)Cv;
                const float2 r0 = *(const float2*)(res + (long long)r * ldc + c);
                const float2 r1 = *(const float2*)(res + (long long)(r + 8) * ldc + c);
                *(float2*)(C + (long long)r * ldc + c)       = make_float2(v0 + r0.x, v1 + r0.y);
                *(float2*)(C + (long long)(r + 8) * ldc + c) = make_float2(v2 + r1.x, v3 + r1.y);
            } else {
                __half* C = (__half*)Cv;
                *(__half2*)(C + (long long)r * ldc + c)       = __floats2half2_rn(v0, v1);
                *(__half2*)(C + (long long)(r + 8) * ldc + c) = __floats2half2_rn(v2, v3);
            }
        }
    }
}

// ---------------- fused flash attention (fp16 MMA + ldmatrix, double-buffered KV) ----------------
// s = (q.k)/8 ; causal j>q -> -inf ; s==0 -> -inf ; softmax ; P.V
#define FBQ  64
#define FBKV 64

template<bool CAUSAL>
__global__ void __launch_bounds__(128, 2)
flash_k(const __half* __restrict__ Qg, const __half* __restrict__ Kg,
        const __half* __restrict__ Vg, __half* __restrict__ Og, int ldq, int ldkv)
{
    __shared__ __align__(128) char sm[32768];   // 2 stages x (8K K + 8K V)
    const uint32_t s0 = s2u(sm);

    const int bz = blockIdx.y;
    const int b = bz / NH, h = bz % NH;
    const int qt = blockIdx.x;
    const int tid = threadIdx.x, lane = tid & 31, w = tid >> 5;
    const int t = lane & 3;
    const int q0 = qt * FBQ;
    const long long rowB = (long long)b * SQ;
    const int hc = h * DK;

    // ---- Q tile -> smem stage0 K area -> A-frags ----
    #pragma unroll
    for (int i = 0; i < 4; i++) {
        const int e = tid + i * 128, r = e >> 3, c = e & 7;
        cp16(s0 + r * 128 + ((c ^ (r & 7)) << 4), Qg + (rowB + q0 + r) * ldq + hc + c * 8);
    }
    CP_COMMIT;
    asm volatile("cp.async.wait_group 0;");
    __syncthreads();
    uint32_t qa[4][4];
    #pragma unroll
    for (int kg = 0; kg < 4; kg++) {
        const int r = w * 16 + (lane & 7) + ((lane >> 3) & 1) * 8;
        const int ch = kg * 2 + (lane >> 4);
        LDSM4(qa[kg][0], qa[kg][1], qa[kg][2], qa[kg][3],
              s0 + r * 128 + ((ch ^ (r & 7)) << 4));
    }
    __syncthreads();

    auto loadKV = [&](int stg, int chk) {
        const int c0 = chk * FBKV;
        const uint32_t sK = s0 + stg * 16384, sV = sK + 8192;
        #pragma unroll
        for (int i = 0; i < 4; i++) {
            const int e = tid + i * 128, r = e >> 3, c = e & 7;
            cp16(sK + r * 128 + ((c ^ (r & 7)) << 4), Kg + (rowB + c0 + r) * ldkv + hc + c * 8);
            cp16(sV + r * 128 + ((c ^ (r & 7)) << 4), Vg + (rowB + c0 + r) * ldkv + hc + c * 8);
        }
    };

    float o[8][4];
    #pragma unroll
    for (int d = 0; d < 8; d++) { o[d][0]=0.f; o[d][1]=0.f; o[d][2]=0.f; o[d][3]=0.f; }
    float m0 = -INFINITY, m1 = -INFINITY, l0 = 0.f, l1 = 0.f;
    const int r0l = q0 + w * 16 + (lane >> 2);
    const int r1l = r0l + 8;

    const int nch = CAUSAL ? (qt + 1) : (SQ / FBKV);
    loadKV(0, 0); CP_COMMIT;

    for (int chk = 0; chk < nch; chk++) {
        const int c0 = chk * FBKV;
        if (chk + 1 < nch) loadKV((chk + 1) & 1, chk + 1);
        CP_COMMIT;
        asm volatile("cp.async.wait_group 1;");
        __syncthreads();
        const uint32_t sK = s0 + (chk & 1) * 16384, sV = sK + 8192;

        // ---- S = Q.K^T ----
        float s[8][4];
        #pragma unroll
        for (int nt = 0; nt < 8; nt++) { s[nt][0]=0.f; s[nt][1]=0.f; s[nt][2]=0.f; s[nt][3]=0.f; }
        #pragma unroll
        for (int kg = 0; kg < 4; kg++) {
            #pragma unroll
            for (int p = 0; p < 4; p++) {
                const int r = p * 16 + (lane & 7) + ((lane >> 4) & 1) * 8;
                const int ch = kg * 2 + ((lane >> 3) & 1);
                uint32_t b0, b1, b2, b3;
                LDSM4(b0, b1, b2, b3, sK + r * 128 + ((ch ^ (r & 7)) << 4));
                MMA_F16(s[2*p],   qa[kg][0], qa[kg][1], qa[kg][2], qa[kg][3], b0, b1);
                MMA_F16(s[2*p+1], qa[kg][0], qa[kg][1], qa[kg][2], qa[kg][3], b2, b3);
            }
        }

        // ---- scale + mask + online softmax ----
        float mx0 = -INFINITY, mx1 = -INFINITY;
        #pragma unroll
        for (int nt = 0; nt < 8; nt++) {
            const int j0 = c0 + nt * 8 + 2 * t, j1 = j0 + 1;
            float v0 = s[nt][0] * 0.125f, v1 = s[nt][1] * 0.125f;
            float v2 = s[nt][2] * 0.125f, v3 = s[nt][3] * 0.125f;
            if ((CAUSAL && j0 > r0l) || v0 == 0.f) v0 = -INFINITY;
            if ((CAUSAL && j1 > r0l) || v1 == 0.f) v1 = -INFINITY;
            if ((CAUSAL && j0 > r1l) || v2 == 0.f) v2 = -INFINITY;
            if ((CAUSAL && j1 > r1l) || v3 == 0.f) v3 = -INFINITY;
            s[nt][0] = v0; s[nt][1] = v1; s[nt][2] = v2; s[nt][3] = v3;
            mx0 = fmaxf(mx0, fmaxf(v0, v1));
            mx1 = fmaxf(mx1, fmaxf(v2, v3));
        }
        mx0 = fmaxf(mx0, __shfl_xor_sync(0xffffffffu, mx0, 1));
        mx0 = fmaxf(mx0, __shfl_xor_sync(0xffffffffu, mx0, 2));
        mx1 = fmaxf(mx1, __shfl_xor_sync(0xffffffffu, mx1, 1));
        mx1 = fmaxf(mx1, __shfl_xor_sync(0xffffffffu, mx1, 2));
        const float mn0 = fmaxf(m0, mx0), mn1 = fmaxf(m1, mx1);
        const float sc0 = __expf(m0 - mn0), sc1 = __expf(m1 - mn1);

        float ps0 = 0.f, ps1 = 0.f;
        #pragma unroll
        for (int nt = 0; nt < 8; nt++) {
            const float p0 = __expf(s[nt][0] - mn0);
            const float p1 = __expf(s[nt][1] - mn0);
            const float p2 = __expf(s[nt][2] - mn1);
            const float p3 = __expf(s[nt][3] - mn1);
            s[nt][0] = p0; s[nt][1] = p1; s[nt][2] = p2; s[nt][3] = p3;
            ps0 += p0 + p1; ps1 += p2 + p3;
        }
        ps0 += __shfl_xor_sync(0xffffffffu, ps0, 1);
        ps0 += __shfl_xor_sync(0xffffffffu, ps0, 2);
        ps1 += __shfl_xor_sync(0xffffffffu, ps1, 1);
        ps1 += __shfl_xor_sync(0xffffffffu, ps1, 2);
        l0 = l0 * sc0 + ps0; l1 = l1 * sc1 + ps1;
        m0 = mn0; m1 = mn1;
        #pragma unroll
        for (int d = 0; d < 8; d++) {
            o[d][0] *= sc0; o[d][1] *= sc0; o[d][2] *= sc1; o[d][3] *= sc1;
        }

        // ---- O += P.V ----
        #pragma unroll
        for (int kg = 0; kg < 4; kg++) {
            const uint32_t a0 = packh2(s[2*kg][0],   s[2*kg][1]);
            const uint32_t a1 = packh2(s[2*kg][2],   s[2*kg][3]);
            const uint32_t a2 = packh2(s[2*kg+1][0], s[2*kg+1][1]);
            const uint32_t a3 = packh2(s[2*kg+1][2], s[2*kg+1][3]);
            #pragma unroll
            for (int p = 0; p < 4; p++) {
                const int r = kg * 16 + (lane & 7) + ((lane >> 3) & 1) * 8;
                const int ch = p * 2 + (lane >> 4);
                uint32_t v0, v1, v2, v3;
                LDSM4T(v0, v1, v2, v3, sV + r * 128 + ((ch ^ (r & 7)) << 4));
                MMA_F16(o[2*p],   a0, a1, a2, a3, v0, v1);
                MMA_F16(o[2*p+1], a0, a1, a2, a3, v2, v3);
            }
        }
        __syncthreads();
    }

    const float i0 = 1.f / l0, i1 = 1.f / l1;
    #pragma unroll
    for (int d = 0; d < 8; d++) {
        const int c = hc + d * 8 + 2 * t;
        *(__half2*)(Og + (rowB + r0l) * DM + c) = __floats2half2_rn(o[d][0] * i0, o[d][1] * i0);
        *(__half2*)(Og + (rowB + r1l) * DM + c) = __floats2half2_rn(o[d][2] * i1, o[d][3] * i1);
    }
}

// ---------------- LayerNorm (fp32 in, fp16 out) ----------------
__global__ __launch_bounds__(256) void ln_k(const float* __restrict__ in,
                                            const float* __restrict__ al,
                                            const float* __restrict__ be,
                                            __half* __restrict__ out)
{
    __shared__ float r1[8], r2[8];
    const long long base = (long long)blockIdx.x * DM;
    const int t = threadIdx.x;
    float2 v = *(const float2*)(in + base + t*2);
    float s = v.x + v.y;
    #pragma unroll
    for (int o=16;o;o>>=1) s += __shfl_xor_sync(0xffffffffu, s, o);
    if ((t&31)==0) r1[t>>5] = s;
    __syncthreads();
    float tot = 0.f;
    #pragma unroll
    for (int w=0;w<8;w++) tot += r1[w];
    const float mu = tot * (1.f/DM);

    const float d0 = v.x - mu, d1 = v.y - mu;
    float ss = d0*d0 + d1*d1;
    #pragma unroll
    for (int o=16;o;o>>=1) ss += __shfl_xor_sync(0xffffffffu, ss, o);
    if ((t&31)==0) r2[t>>5] = ss;
    __syncthreads();
    float tot2 = 0.f;
    #pragma unroll
    for (int w=0;w<8;w++) tot2 += r2[w];
    const float sd  = sqrtf(tot2 * (1.f/(DM-1)));
    const float inv = 1.f/(sd + EPSF);

    const float a0 = al[t*2], a1 = al[t*2+1];
    const float b0 = be[t*2], b1 = be[t*2+1];
    *(__half2*)(out + base + t*2) = __floats2half2_rn(a0*d0*inv + b0, a1*d1*inv + b1);
}

// ---------------- prep kernels ----------------
// batched 512x512 transpose+fp16: 8 matrices in one launch (z dim)
struct TrBatch { const float* src[8]; __half* dst[8]; };

__global__ __launch_bounds__(256) void tr8_k(TrBatch tb)
{
    __shared__ float t[32][33];
    const float* src = tb.src[blockIdx.z];
    __half* dst = tb.dst[blockIdx.z];
    const int nb = blockIdx.x*32, kb = blockIdx.y*32;
    const int tx = threadIdx.x & 31, ty = threadIdx.x >> 5;
    #pragma unroll
    for (int i = 0; i < 32; i += 8)
        t[ty+i][tx] = src[(long long)(kb+ty+i)*DM + nb+tx];
    __syncthreads();
    #pragma unroll
    for (int i = 0; i < 32; i += 8)
        dst[(long long)(nb+ty+i)*DM + kb+tx] = __float2half(t[tx][ty+i]);
}

// generic transpose + fp16: src fp32 [Kd][Nd] -> dst fp16 [Nd][Kd]
__global__ __launch_bounds__(256) void tr_k(const float* __restrict__ src,
                                            __half* __restrict__ dst, int Kd, int Nd)
{
    __shared__ float t[32][33];
    const int nb = blockIdx.x*32, kb = blockIdx.y*32;
    const int tx = threadIdx.x & 31, ty = threadIdx.x >> 5;
    #pragma unroll
    for (int i = 0; i < 32; i += 8)
        t[ty+i][tx] = src[(long long)(kb+ty+i)*Nd + nb+tx];
    __syncthreads();
    #pragma unroll
    for (int i = 0; i < 32; i += 8)
        dst[(long long)(nb+ty+i)*Kd + kb+tx] = __float2half(t[tx][ty+i]);
}

__global__ void rc_k(const float* __restrict__ src, __half* __restrict__ dst, int n)
{
    const int i = blockIdx.x*256 + threadIdx.x;
    if (i < n) dst[i] = __float2half(src[i]);
}

// ---------------- launch ----------------
extern "C" void kernel_launch(void* const* d_in, const int* in_sizes, int n_in,
                              void* d_out, int out_size)
{
    const float* x    = (const float*)d_in[0];
    const float* mem  = (const float*)d_in[1];
    const float* ln1a = (const float*)d_in[2];
    const float* ln1b = (const float*)d_in[3];
    const float* ln2a = (const float*)d_in[4];
    const float* ln2b = (const float*)d_in[5];
    const float* ln3a = (const float*)d_in[6];
    const float* ln3b = (const float*)d_in[7];
    const float* wq1  = (const float*)d_in[8];
    const float* wk1  = (const float*)d_in[9];
    const float* wv1  = (const float*)d_in[10];
    const float* wo1  = (const float*)d_in[11];
    const float* bo1  = (const float*)d_in[12];
    const float* wq2  = (const float*)d_in[13];
    const float* wk2  = (const float*)d_in[14];
    const float* wv2  = (const float*)d_in[15];
    const float* wo2  = (const float*)d_in[16];
    const float* bo2  = (const float*)d_in[17];
    const float* fw1  = (const float*)d_in[18];
    const float* fb1  = (const float*)d_in[19];
    const float* fw2  = (const float*)d_in[20];
    const float* fb2  = (const float*)d_in[21];
    float* out = (float*)d_out;

    float* px;
    __half *px2h,*pqkvh,*pqh,*pkvh,*pctxh,*pffh,*pmemh;
    __half *pwqkvt,*pwq2t,*pwkvt,*pwo1t,*pwo2t,*pfw1t,*pfw2t;
    cudaGetSymbolAddress((void**)&px,    g_x);
    cudaGetSymbolAddress((void**)&px2h,  g_x2h);
    cudaGetSymbolAddress((void**)&pqkvh, g_qkvh);
    cudaGetSymbolAddress((void**)&pqh,   g_qh);
    cudaGetSymbolAddress((void**)&pkvh,  g_kvh);
    cudaGetSymbolAddress((void**)&pctxh, g_ctxh);
    cudaGetSymbolAddress((void**)&pffh,  g_ffh);
    cudaGetSymbolAddress((void**)&pmemh, g_memh);
    cudaGetSymbolAddress((void**)&pwqkvt,g_wqkvt);
    cudaGetSymbolAddress((void**)&pwq2t, g_wq2t);
    cudaGetSymbolAddress((void**)&pwkvt, g_wkvt);
    cudaGetSymbolAddress((void**)&pwo1t, g_wo1t);
    cudaGetSymbolAddress((void**)&pwo2t, g_wo2t);
    cudaGetSymbolAddress((void**)&pfw1t, g_fw1t);
    cudaGetSymbolAddress((void**)&pfw2t, g_fw2t);

    cudaFuncSetAttribute(hgemm<0>, cudaFuncAttributeMaxDynamicSharedMemorySize, GSMEM);
    cudaFuncSetAttribute(hgemm<2>, cudaFuncAttributeMaxDynamicSharedMemorySize, GSMEM);
    cudaFuncSetAttribute(hgemm<3>, cudaFuncAttributeMaxDynamicSharedMemorySize, GSMEM);

    // ---- prep: batched transpose of the 8 512x512 weights, 2 FFN transposes, mem convert ----
    TrBatch tb8;
    tb8.src[0] = wq1; tb8.dst[0] = pwqkvt + 0*DM*DM;
    tb8.src[1] = wk1; tb8.dst[1] = pwqkvt + 1*DM*DM;
    tb8.src[2] = wv1; tb8.dst[2] = pwqkvt + 2*DM*DM;
    tb8.src[3] = wq2; tb8.dst[3] = pwq2t;
    tb8.src[4] = wk2; tb8.dst[4] = pwkvt + 0*DM*DM;
    tb8.src[5] = wv2; tb8.dst[5] = pwkvt + 1*DM*DM;
    tb8.src[6] = wo1; tb8.dst[6] = pwo1t;
    tb8.src[7] = wo2; tb8.dst[7] = pwo2t;
    tr8_k<<<dim3(16, 16, 8), 256>>>(tb8);
    tr_k<<<dim3(DFF/32, DM/32), 256>>>(fw1, pfw1t, DM, DFF);
    tr_k<<<dim3(DM/32, DFF/32), 256>>>(fw2, pfw2t, DFF, DM);
    rc_k<<<(RT*DM+255)/256, 256>>>(mem, pmemh, RT*DM);

    const dim3 gQKV(12, 32), gP(4, 32), gKV(8, 32), gFF1(16, 32);
    const dim3 gFlash(SQ/FBQ, NB*NH);

    // ---- self attention (residual read directly from input x; writes px) ----
    ln_k<<<RT, 256>>>(x, ln1a, ln1b, px2h);
    hgemm<0><<<gQKV, 256, GSMEM>>>(px2h, pwqkvt, pqkvh, nullptr, nullptr, DM, 3*DM);
    flash_k<true><<<gFlash, 128>>>(pqkvh, pqkvh + DM, pqkvh + 2*DM, pctxh, 3*DM, 3*DM);
    hgemm<3><<<gP, 256, GSMEM>>>(pctxh, pwo1t, px, bo1, x, DM, DM);

    // ---- cross attention ----
    ln_k<<<RT, 256>>>(px, ln2a, ln2b, px2h);
    hgemm<0><<<gP, 256, GSMEM>>>(px2h, pwq2t, pqh, nullptr, nullptr, DM, DM);
    hgemm<0><<<gKV, 256, GSMEM>>>(pmemh, pwkvt, pkvh, nullptr, nullptr, DM, 2*DM);
    flash_k<false><<<gFlash, 128>>>(pqh, pkvh, pkvh + DM, pctxh, DM, 2*DM);
    hgemm<3><<<gP, 256, GSMEM>>>(pctxh, pwo2t, px, bo2, px, DM, DM);

    // ---- feed forward ----
    ln_k<<<RT, 256>>>(px, ln3a, ln3b, px2h);
    hgemm<2><<<gFF1, 256, GSMEM>>>(px2h, pfw1t, pffh, fb1, nullptr, DM, DFF);
    hgemm<3><<<gP, 256, GSMEM>>>(pffh, pfw2t, out, fb2, px, DFF, DM);
}

// round 10
// speedup vs baseline: 8.1229x; 1.0200x over previous
#include <cuda_runtime.h>
#include <cuda_fp16.h>
#include <math.h>
#include <stdint.h>

#define DM   512
#define NH   8
#define DK   64
#define DFF  2048
#define NB   2
#define SQ   2048
#define RT   (NB*SQ)
#define EPSF 1e-6f

// ---------------- scratch ----------------
__device__ float  g_x   [RT*DM];          // fp32 residual stream
__device__ __half g_x2h [RT*DM];          // LN outputs (GEMM A)
__device__ __half g_qkvh[RT*3*DM];
__device__ __half g_qh  [RT*DM];
__device__ __half g_kvh [RT*2*DM];
__device__ __half g_ctxh[RT*DM];
__device__ __half g_ffh [RT*DFF];
__device__ __half g_memh[RT*DM];
// transposed ([N,K]) fp16 weights
__device__ __half g_wqkvt[3*DM*DM];
__device__ __half g_wq2t [DM*DM];
__device__ __half g_wkvt [2*DM*DM];
__device__ __half g_wo1t [DM*DM];
__device__ __half g_wo2t [DM*DM];
__device__ __half g_fw1t [DFF*DM];
__device__ __half g_fw2t [DM*DFF];

__device__ __forceinline__ uint32_t s2u(const void* p) {
    uint32_t a;
    asm("{ .reg .u64 t; cvta.to.shared.u64 t, %1; cvt.u32.u64 %0, t; }" : "=r"(a) : "l"(p));
    return a;
}
__device__ __forceinline__ uint32_t packh2(float a, float b) {
    __half2 h = __floats2half2_rn(a, b);
    return *(uint32_t*)&h;
}
__device__ __forceinline__ void cp16(uint32_t dst, const void* src) {
    asm volatile("cp.async.ca.shared.global [%0], [%1], 16;" :: "r"(dst), "l"(src));
}
#define CP_COMMIT asm volatile("cp.async.commit_group;")

#define MMA_F16(acc, a0,a1,a2,a3, b0,b1) \
    asm volatile("mma.sync.aligned.m16n8k16.row.col.f32.f16.f16.f32 " \
                 "{%0,%1,%2,%3}, {%4,%5,%6,%7}, {%8,%9}, {%0,%1,%2,%3};" \
                 : "+f"(acc[0]), "+f"(acc[1]), "+f"(acc[2]), "+f"(acc[3]) \
                 : "r"(a0), "r"(a1), "r"(a2), "r"(a3), "r"(b0), "r"(b1))

#define LDSM4(r0,r1,r2,r3, addr) \
    asm volatile("ldmatrix.sync.aligned.m8n8.x4.shared.b16 {%0,%1,%2,%3}, [%4];" \
                 : "=r"(r0), "=r"(r1), "=r"(r2), "=r"(r3) : "r"(addr))
#define LDSM4T(r0,r1,r2,r3, addr) \
    asm volatile("ldmatrix.sync.aligned.m8n8.x4.trans.shared.b16 {%0,%1,%2,%3}, [%4];" \
                 : "=r"(r0), "=r"(r1), "=r"(r2), "=r"(r3) : "r"(addr))

// ---------------- fp16 ldmatrix GEMM ----------------
// C[4096, Nout] = A[4096, K](f16) * Bt[Nout, K](f16)^T
// 128x128 tiles, BK=64 halves (128B SW128 rows), 3-stage cp.async, 256 thr (2x4 warps, 64x32).
// FUSE: 0=plain (f16 out), 2=bias+relu (f16 out), 3=bias+residual (f32 out)
#define STB 32768                   // bytes per stage (A 16K + B 16K)
#define GSMEM (3*STB)

template<int FUSE>
__global__ void __launch_bounds__(256, 2)
hgemm(const __half* __restrict__ A, const __half* __restrict__ Bt, void* __restrict__ Cv,
      const float* __restrict__ bias, const float* __restrict__ res, int K, int ldc)
{
    extern __shared__ char smem[];
    const uint32_t sb = s2u(smem);
    const int tid = threadIdx.x, lane = tid & 31, wid = tid >> 5;
    const int wm = wid >> 2, wn = wid & 3;
    const int row0 = blockIdx.y * 128, col0 = blockIdx.x * 128;

    auto loadA = [&](int s, int it) {
        const __half* Ag = A + (long long)row0 * K + it * 64;
        const uint32_t d0 = sb + s * STB;
        #pragma unroll
        for (int i = 0; i < 4; i++) {
            const int e = tid + i * 256, r = e >> 3, c = e & 7;
            cp16(d0 + r * 128 + ((c ^ (r & 7)) << 4), Ag + (long long)r * K + c * 8);
        }
    };
    auto loadB = [&](int s, int it) {
        const __half* Bg = Bt + (long long)col0 * K + it * 64;
        const uint32_t d0 = sb + s * STB + 16384;
        #pragma unroll
        for (int i = 0; i < 4; i++) {
            const int e = tid + i * 256, r = e >> 3, c = e & 7;
            cp16(d0 + r * 128 + ((c ^ (r & 7)) << 4), Bg + (long long)r * K + c * 8);
        }
    };

    float acc[4][4][4];
    #pragma unroll
    for (int i = 0; i < 4; i++)
        #pragma unroll
        for (int j = 0; j < 4; j++)
            #pragma unroll
            for (int q = 0; q < 4; q++) acc[i][j][q] = 0.f;

    const int NIT = K / 64;
    loadA(0, 0); loadB(0, 0); CP_COMMIT;
    loadA(1, 1); loadB(1, 1); CP_COMMIT;

    for (int it = 0; it < NIT; it++) {
        asm volatile("cp.async.wait_group 1;");
        __syncthreads();
        const int j = it + 2;
        if (j < NIT) { loadA(j % 3, j); loadB(j % 3, j); }
        CP_COMMIT;

        const uint32_t sa = sb + (it % 3) * STB;
        const uint32_t sB = sa + 16384;
        #pragma unroll
        for (int kg = 0; kg < 4; kg++) {
            uint32_t af[4][4], bf[4][2];
            #pragma unroll
            for (int mt = 0; mt < 4; mt++) {
                const int r = wm * 64 + mt * 16 + (lane & 7) + ((lane >> 3) & 1) * 8;
                const int ch = kg * 2 + (lane >> 4);
                LDSM4(af[mt][0], af[mt][1], af[mt][2], af[mt][3],
                      sa + r * 128 + ((ch ^ (r & 7)) << 4));
            }
            #pragma unroll
            for (int p = 0; p < 2; p++) {
                const int r = wn * 32 + p * 16 + (lane & 7) + ((lane >> 4) & 1) * 8;
                const int ch = kg * 2 + ((lane >> 3) & 1);
                uint32_t b0, b1, b2, b3;
                LDSM4(b0, b1, b2, b3, sB + r * 128 + ((ch ^ (r & 7)) << 4));
                bf[2*p][0] = b0; bf[2*p][1] = b1; bf[2*p+1][0] = b2; bf[2*p+1][1] = b3;
            }
            #pragma unroll
            for (int mt = 0; mt < 4; mt++)
                #pragma unroll
                for (int nt = 0; nt < 4; nt++)
                    MMA_F16(acc[mt][nt], af[mt][0], af[mt][1], af[mt][2], af[mt][3],
                            bf[nt][0], bf[nt][1]);
        }
    }

    // epilogue
    #pragma unroll
    for (int mt = 0; mt < 4; mt++) {
        #pragma unroll
        for (int nt = 0; nt < 4; nt++) {
            const int r = row0 + wm * 64 + mt * 16 + (lane >> 2);
            const int c = col0 + wn * 32 + nt * 8 + 2 * (lane & 3);
            float v0 = acc[mt][nt][0], v1 = acc[mt][nt][1];
            float v2 = acc[mt][nt][2], v3 = acc[mt][nt][3];
            if (FUSE >= 2) {
                const float b0 = bias[c], b1 = bias[c + 1];
                v0 += b0; v1 += b1; v2 += b0; v3 += b1;
            }
            if (FUSE == 2) {
                v0 = fmaxf(v0, 0.f); v1 = fmaxf(v1, 0.f);
                v2 = fmaxf(v2, 0.f); v3 = fmaxf(v3, 0.f);
            }
            if (FUSE == 3) {
                float* C = (float*)Cv;
                const float2 r0 = *(const float2*)(res + (long long)r * ldc + c);
                const float2 r1 = *(const float2*)(res + (long long)(r + 8) * ldc + c);
                *(float2*)(C + (long long)r * ldc + c)       = make_float2(v0 + r0.x, v1 + r0.y);
                *(float2*)(C + (long long)(r + 8) * ldc + c) = make_float2(v2 + r1.x, v3 + r1.y);
            } else {
                __half* C = (__half*)Cv;
                *(__half2*)(C + (long long)r * ldc + c)       = __floats2half2_rn(v0, v1);
                *(__half2*)(C + (long long)(r + 8) * ldc + c) = __floats2half2_rn(v2, v3);
            }
        }
    }
}

// ---------------- fused flash attention (fp16 MMA + ldmatrix, double-buffered KV) ----------------
// s = (q.k)/8 ; causal j>q -> -inf ; s==0 -> -inf ; softmax ; P.V
#define FBQ  64
#define FBKV 64

template<bool CAUSAL>
__global__ void __launch_bounds__(128, 2)
flash_k(const __half* __restrict__ Qg, const __half* __restrict__ Kg,
        const __half* __restrict__ Vg, __half* __restrict__ Og, int ldq, int ldkv)
{
    __shared__ __align__(128) char sm[32768];   // 2 stages x (8K K + 8K V)
    const uint32_t s0 = s2u(sm);

    const int bz = blockIdx.y;
    const int b = bz / NH, h = bz % NH;
    const int qt = blockIdx.x;
    const int tid = threadIdx.x, lane = tid & 31, w = tid >> 5;
    const int t = lane & 3;
    const int q0 = qt * FBQ;
    const long long rowB = (long long)b * SQ;
    const int hc = h * DK;

    // ---- Q tile -> smem stage0 K area -> A-frags ----
    #pragma unroll
    for (int i = 0; i < 4; i++) {
        const int e = tid + i * 128, r = e >> 3, c = e & 7;
        cp16(s0 + r * 128 + ((c ^ (r & 7)) << 4), Qg + (rowB + q0 + r) * ldq + hc + c * 8);
    }
    CP_COMMIT;
    asm volatile("cp.async.wait_group 0;");
    __syncthreads();
    uint32_t qa[4][4];
    #pragma unroll
    for (int kg = 0; kg < 4; kg++) {
        const int r = w * 16 + (lane & 7) + ((lane >> 3) & 1) * 8;
        const int ch = kg * 2 + (lane >> 4);
        LDSM4(qa[kg][0], qa[kg][1], qa[kg][2], qa[kg][3],
              s0 + r * 128 + ((ch ^ (r & 7)) << 4));
    }
    __syncthreads();

    auto loadKV = [&](int stg, int chk) {
        const int c0 = chk * FBKV;
        const uint32_t sK = s0 + stg * 16384, sV = sK + 8192;
        #pragma unroll
        for (int i = 0; i < 4; i++) {
            const int e = tid + i * 128, r = e >> 3, c = e & 7;
            cp16(sK + r * 128 + ((c ^ (r & 7)) << 4), Kg + (rowB + c0 + r) * ldkv + hc + c * 8);
            cp16(sV + r * 128 + ((c ^ (r & 7)) << 4), Vg + (rowB + c0 + r) * ldkv + hc + c * 8);
        }
    };

    float o[8][4];
    #pragma unroll
    for (int d = 0; d < 8; d++) { o[d][0]=0.f; o[d][1]=0.f; o[d][2]=0.f; o[d][3]=0.f; }
    float m0 = -INFINITY, m1 = -INFINITY, l0 = 0.f, l1 = 0.f;
    const int r0l = q0 + w * 16 + (lane >> 2);
    const int r1l = r0l + 8;

    const int nch = CAUSAL ? (qt + 1) : (SQ / FBKV);
    loadKV(0, 0); CP_COMMIT;

    for (int chk = 0; chk < nch; chk++) {
        const int c0 = chk * FBKV;
        if (chk + 1 < nch) loadKV((chk + 1) & 1, chk + 1);
        CP_COMMIT;
        asm volatile("cp.async.wait_group 1;");
        __syncthreads();
        const uint32_t sK = s0 + (chk & 1) * 16384, sV = sK + 8192;

        // ---- S = Q.K^T ----
        float s[8][4];
        #pragma unroll
        for (int nt = 0; nt < 8; nt++) { s[nt][0]=0.f; s[nt][1]=0.f; s[nt][2]=0.f; s[nt][3]=0.f; }
        #pragma unroll
        for (int kg = 0; kg < 4; kg++) {
            #pragma unroll
            for (int p = 0; p < 4; p++) {
                const int r = p * 16 + (lane & 7) + ((lane >> 4) & 1) * 8;
                const int ch = kg * 2 + ((lane >> 3) & 1);
                uint32_t b0, b1, b2, b3;
                LDSM4(b0, b1, b2, b3, sK + r * 128 + ((ch ^ (r & 7)) << 4));
                MMA_F16(s[2*p],   qa[kg][0], qa[kg][1], qa[kg][2], qa[kg][3], b0, b1);
                MMA_F16(s[2*p+1], qa[kg][0], qa[kg][1], qa[kg][2], qa[kg][3], b2, b3);
            }
        }

        // ---- scale + mask + online softmax ----
        float mx0 = -INFINITY, mx1 = -INFINITY;
        #pragma unroll
        for (int nt = 0; nt < 8; nt++) {
            const int j0 = c0 + nt * 8 + 2 * t, j1 = j0 + 1;
            float v0 = s[nt][0] * 0.125f, v1 = s[nt][1] * 0.125f;
            float v2 = s[nt][2] * 0.125f, v3 = s[nt][3] * 0.125f;
            if ((CAUSAL && j0 > r0l) || v0 == 0.f) v0 = -INFINITY;
            if ((CAUSAL && j1 > r0l) || v1 == 0.f) v1 = -INFINITY;
            if ((CAUSAL && j0 > r1l) || v2 == 0.f) v2 = -INFINITY;
            if ((CAUSAL && j1 > r1l) || v3 == 0.f) v3 = -INFINITY;
            s[nt][0] = v0; s[nt][1] = v1; s[nt][2] = v2; s[nt][3] = v3;
            mx0 = fmaxf(mx0, fmaxf(v0, v1));
            mx1 = fmaxf(mx1, fmaxf(v2, v3));
        }
        mx0 = fmaxf(mx0, __shfl_xor_sync(0xffffffffu, mx0, 1));
        mx0 = fmaxf(mx0, __shfl_xor_sync(0xffffffffu, mx0, 2));
        mx1 = fmaxf(mx1, __shfl_xor_sync(0xffffffffu, mx1, 1));
        mx1 = fmaxf(mx1, __shfl_xor_sync(0xffffffffu, mx1, 2));
        const float mn0 = fmaxf(m0, mx0), mn1 = fmaxf(m1, mx1);
        const float sc0 = __expf(m0 - mn0), sc1 = __expf(m1 - mn1);

        float ps0 = 0.f, ps1 = 0.f;
        #pragma unroll
        for (int nt = 0; nt < 8; nt++) {
            const float p0 = __expf(s[nt][0] - mn0);
            const float p1 = __expf(s[nt][1] - mn0);
            const float p2 = __expf(s[nt][2] - mn1);
            const float p3 = __expf(s[nt][3] - mn1);
            s[nt][0] = p0; s[nt][1] = p1; s[nt][2] = p2; s[nt][3] = p3;
            ps0 += p0 + p1; ps1 += p2 + p3;
        }
        ps0 += __shfl_xor_sync(0xffffffffu, ps0, 1);
        ps0 += __shfl_xor_sync(0xffffffffu, ps0, 2);
        ps1 += __shfl_xor_sync(0xffffffffu, ps1, 1);
        ps1 += __shfl_xor_sync(0xffffffffu, ps1, 2);
        l0 = l0 * sc0 + ps0; l1 = l1 * sc1 + ps1;
        m0 = mn0; m1 = mn1;
        #pragma unroll
        for (int d = 0; d < 8; d++) {
            o[d][0] *= sc0; o[d][1] *= sc0; o[d][2] *= sc1; o[d][3] *= sc1;
        }

        // ---- O += P.V ----
        #pragma unroll
        for (int kg = 0; kg < 4; kg++) {
            const uint32_t a0 = packh2(s[2*kg][0],   s[2*kg][1]);
            const uint32_t a1 = packh2(s[2*kg][2],   s[2*kg][3]);
            const uint32_t a2 = packh2(s[2*kg+1][0], s[2*kg+1][1]);
            const uint32_t a3 = packh2(s[2*kg+1][2], s[2*kg+1][3]);
            #pragma unroll
            for (int p = 0; p < 4; p++) {
                const int r = kg * 16 + (lane & 7) + ((lane >> 3) & 1) * 8;
                const int ch = p * 2 + (lane >> 4);
                uint32_t v0, v1, v2, v3;
                LDSM4T(v0, v1, v2, v3, sV + r * 128 + ((ch ^ (r & 7)) << 4));
                MMA_F16(o[2*p],   a0, a1, a2, a3, v0, v1);
                MMA_F16(o[2*p+1], a0, a1, a2, a3, v2, v3);
            }
        }
        __syncthreads();
    }

    const float i0 = 1.f / l0, i1 = 1.f / l1;
    #pragma unroll
    for (int d = 0; d < 8; d++) {
        const int c = hc + d * 8 + 2 * t;
        *(__half2*)(Og + (rowB + r0l) * DM + c) = __floats2half2_rn(o[d][0] * i0, o[d][1] * i0);
        *(__half2*)(Og + (rowB + r1l) * DM + c) = __floats2half2_rn(o[d][2] * i1, o[d][3] * i1);
    }
}

// ---------------- LayerNorm (fp32 in, fp16 out) ----------------
__global__ __launch_bounds__(256) void ln_k(const float* __restrict__ in,
                                            const float* __restrict__ al,
                                            const float* __restrict__ be,
                                            __half* __restrict__ out)
{
    __shared__ float r1[8], r2[8];
    const long long base = (long long)blockIdx.x * DM;
    const int t = threadIdx.x;
    float2 v = *(const float2*)(in + base + t*2);
    float s = v.x + v.y;
    #pragma unroll
    for (int o=16;o;o>>=1) s += __shfl_xor_sync(0xffffffffu, s, o);
    if ((t&31)==0) r1[t>>5] = s;
    __syncthreads();
    float tot = 0.f;
    #pragma unroll
    for (int w=0;w<8;w++) tot += r1[w];
    const float mu = tot * (1.f/DM);

    const float d0 = v.x - mu, d1 = v.y - mu;
    float ss = d0*d0 + d1*d1;
    #pragma unroll
    for (int o=16;o;o>>=1) ss += __shfl_xor_sync(0xffffffffu, ss, o);
    if ((t&31)==0) r2[t>>5] = ss;
    __syncthreads();
    float tot2 = 0.f;
    #pragma unroll
    for (int w=0;w<8;w++) tot2 += r2[w];
    const float sd  = sqrtf(tot2 * (1.f/(DM-1)));
    const float inv = 1.f/(sd + EPSF);

    const float a0 = al[t*2], a1 = al[t*2+1];
    const float b0 = be[t*2], b1 = be[t*2+1];
    *(__half2*)(out + base + t*2) = __floats2half2_rn(a0*d0*inv + b0, a1*d1*inv + b1);
}

// ---------------- prep kernels ----------------
// batched 512x512 transpose+fp16: 8 matrices in one launch (z dim)
struct TrBatch { const float* src[8]; __half* dst[8]; };

__global__ __launch_bounds__(256) void tr8_k(TrBatch tb)
{
    __shared__ float t[32][33];
    const float* src = tb.src[blockIdx.z];
    __half* dst = tb.dst[blockIdx.z];
    const int nb = blockIdx.x*32, kb = blockIdx.y*32;
    const int tx = threadIdx.x & 31, ty = threadIdx.x >> 5;
    #pragma unroll
    for (int i = 0; i < 32; i += 8)
        t[ty+i][tx] = src[(long long)(kb+ty+i)*DM + nb+tx];
    __syncthreads();
    #pragma unroll
    for (int i = 0; i < 32; i += 8)
        dst[(long long)(nb+ty+i)*DM + kb+tx] = __float2half(t[tx][ty+i]);
}

// generic transpose + fp16: src fp32 [Kd][Nd] -> dst fp16 [Nd][Kd]
__global__ __launch_bounds__(256) void tr_k(const float* __restrict__ src,
                                            __half* __restrict__ dst, int Kd, int Nd)
{
    __shared__ float t[32][33];
    const int nb = blockIdx.x*32, kb = blockIdx.y*32;
    const int tx = threadIdx.x & 31, ty = threadIdx.x >> 5;
    #pragma unroll
    for (int i = 0; i < 32; i += 8)
        t[ty+i][tx] = src[(long long)(kb+ty+i)*Nd + nb+tx];
    __syncthreads();
    #pragma unroll
    for (int i = 0; i < 32; i += 8)
        dst[(long long)(nb+ty+i)*Kd + kb+tx] = __float2half(t[tx][ty+i]);
}

__global__ void rc_k(const float* __restrict__ src, __half* __restrict__ dst, int n)
{
    const int i = blockIdx.x*256 + threadIdx.x;
    if (i < n) dst[i] = __float2half(src[i]);
}

// ---------------- launch ----------------
extern "C" void kernel_launch(void* const* d_in, const int* in_sizes, int n_in,
                              void* d_out, int out_size)
{
    const float* x    = (const float*)d_in[0];
    const float* mem  = (const float*)d_in[1];
    const float* ln1a = (const float*)d_in[2];
    const float* ln1b = (const float*)d_in[3];
    const float* ln2a = (const float*)d_in[4];
    const float* ln2b = (const float*)d_in[5];
    const float* ln3a = (const float*)d_in[6];
    const float* ln3b = (const float*)d_in[7];
    const float* wq1  = (const float*)d_in[8];
    const float* wk1  = (const float*)d_in[9];
    const float* wv1  = (const float*)d_in[10];
    const float* wo1  = (const float*)d_in[11];
    const float* bo1  = (const float*)d_in[12];
    const float* wq2  = (const float*)d_in[13];
    const float* wk2  = (const float*)d_in[14];
    const float* wv2  = (const float*)d_in[15];
    const float* wo2  = (const float*)d_in[16];
    const float* bo2  = (const float*)d_in[17];
    const float* fw1  = (const float*)d_in[18];
    const float* fb1  = (const float*)d_in[19];
    const float* fw2  = (const float*)d_in[20];
    const float* fb2  = (const float*)d_in[21];
    float* out = (float*)d_out;

    float* px;
    __half *px2h,*pqkvh,*pqh,*pkvh,*pctxh,*pffh,*pmemh;
    __half *pwqkvt,*pwq2t,*pwkvt,*pwo1t,*pwo2t,*pfw1t,*pfw2t;
    cudaGetSymbolAddress((void**)&px,    g_x);
    cudaGetSymbolAddress((void**)&px2h,  g_x2h);
    cudaGetSymbolAddress((void**)&pqkvh, g_qkvh);
    cudaGetSymbolAddress((void**)&pqh,   g_qh);
    cudaGetSymbolAddress((void**)&pkvh,  g_kvh);
    cudaGetSymbolAddress((void**)&pctxh, g_ctxh);
    cudaGetSymbolAddress((void**)&pffh,  g_ffh);
    cudaGetSymbolAddress((void**)&pmemh, g_memh);
    cudaGetSymbolAddress((void**)&pwqkvt,g_wqkvt);
    cudaGetSymbolAddress((void**)&pwq2t, g_wq2t);
    cudaGetSymbolAddress((void**)&pwkvt, g_wkvt);
    cudaGetSymbolAddress((void**)&pwo1t, g_wo1t);
    cudaGetSymbolAddress((void**)&pwo2t, g_wo2t);
    cudaGetSymbolAddress((void**)&pfw1t, g_fw1t);
    cudaGetSymbolAddress((void**)&pfw2t, g_fw2t);

    cudaFuncSetAttribute(hgemm<0>, cudaFuncAttributeMaxDynamicSharedMemorySize, GSMEM);
    cudaFuncSetAttribute(hgemm<2>, cudaFuncAttributeMaxDynamicSharedMemorySize, GSMEM);
    cudaFuncSetAttribute(hgemm<3>, cudaFuncAttributeMaxDynamicSharedMemorySize, GSMEM);

    // side stream + fork/join events. Created ONCE on the first (uncaptured)
    // correctness call; during graph capture only captured ops (launches,
    // event record/wait) execute.
    static cudaStream_t sSide = nullptr;
    static cudaEvent_t  eFork = nullptr, eW = nullptr, eSide = nullptr;
    if (!sSide) {
        cudaStreamCreateWithFlags(&sSide, cudaStreamNonBlocking);
        cudaEventCreateWithFlags(&eFork, cudaEventDisableTiming);
        cudaEventCreateWithFlags(&eW,    cudaEventDisableTiming);
        cudaEventCreateWithFlags(&eSide, cudaEventDisableTiming);
    }

    // ---- fork: side chain (weight prep + mem convert + cross-KV projection) ----
    cudaEventRecord(eFork, 0);
    cudaStreamWaitEvent(sSide, eFork, 0);

    TrBatch tb8;
    tb8.src[0] = wq1; tb8.dst[0] = pwqkvt + 0*DM*DM;
    tb8.src[1] = wk1; tb8.dst[1] = pwqkvt + 1*DM*DM;
    tb8.src[2] = wv1; tb8.dst[2] = pwqkvt + 2*DM*DM;
    tb8.src[3] = wq2; tb8.dst[3] = pwq2t;
    tb8.src[4] = wk2; tb8.dst[4] = pwkvt + 0*DM*DM;
    tb8.src[5] = wv2; tb8.dst[5] = pwkvt + 1*DM*DM;
    tb8.src[6] = wo1; tb8.dst[6] = pwo1t;
    tb8.src[7] = wo2; tb8.dst[7] = pwo2t;
    tr8_k<<<dim3(16, 16, 8), 256, 0, sSide>>>(tb8);
    cudaEventRecord(eW, sSide);                      // square weights ready
    tr_k<<<dim3(DFF/32, DM/32), 256, 0, sSide>>>(fw1, pfw1t, DM, DFF);
    tr_k<<<dim3(DM/32, DFF/32), 256, 0, sSide>>>(fw2, pfw2t, DFF, DM);
    rc_k<<<(RT*DM+255)/256, 256, 0, sSide>>>(mem, pmemh, RT*DM);
    hgemm<0><<<dim3(8, 32), 256, GSMEM, sSide>>>(pmemh, pwkvt, pkvh, nullptr, nullptr, DM, 2*DM);
    cudaEventRecord(eSide, sSide);                   // kv + FFN weights ready

    const dim3 gQKV(12, 32), gP(4, 32), gFF1(16, 32);
    const dim3 gFlash(SQ/FBQ, NB*NH);

    // ---- main chain ----
    // self attention (residual read directly from input x; writes px)
    ln_k<<<RT, 256>>>(x, ln1a, ln1b, px2h);
    cudaStreamWaitEvent(0, eW, 0);                   // need wqkvt (+wo1t later)
    hgemm<0><<<gQKV, 256, GSMEM>>>(px2h, pwqkvt, pqkvh, nullptr, nullptr, DM, 3*DM);
    flash_k<true><<<gFlash, 128>>>(pqkvh, pqkvh + DM, pqkvh + 2*DM, pctxh, 3*DM, 3*DM);
    hgemm<3><<<gP, 256, GSMEM>>>(pctxh, pwo1t, px, bo1, x, DM, DM);

    // cross attention
    ln_k<<<RT, 256>>>(px, ln2a, ln2b, px2h);
    hgemm<0><<<gP, 256, GSMEM>>>(px2h, pwq2t, pqh, nullptr, nullptr, DM, DM);
    cudaStreamWaitEvent(0, eSide, 0);                // need pkvh (+fw1t/fw2t later)
    flash_k<false><<<gFlash, 128>>>(pqh, pkvh, pkvh + DM, pctxh, DM, 2*DM);
    hgemm<3><<<gP, 256, GSMEM>>>(pctxh, pwo2t, px, bo2, px, DM, DM);

    // feed forward
    ln_k<<<RT, 256>>>(px, ln3a, ln3b, px2h);
    hgemm<2><<<gFF1, 256, GSMEM>>>(px2h, pfw1t, pffh, fb1, nullptr, DM, DFF);
    hgemm<3><<<gP, 256, GSMEM>>>(pffh, pfw2t, out, fb2, px, DFF, DM);
}

// round 11
// speedup vs baseline: 8.5869x; 1.0571x over previous
#include <cuda_runtime.h>
#include <cuda_fp16.h>
#include <math.h>
#include <stdint.h>

#define DM   512
#define NH   8
#define DK   64
#define DFF  2048
#define NB   2
#define SQ   2048
#define RT   (NB*SQ)
#define EPSF 1e-6f

// ---------------- scratch ----------------
__device__ float  g_x   [RT*DM];          // fp32 residual stream
__device__ __half g_x2h [RT*DM];          // LN outputs (GEMM A)
__device__ __half g_qkvh[RT*3*DM];
__device__ __half g_qh  [RT*DM];
__device__ __half g_kvh [RT*2*DM];
__device__ __half g_ctxh[RT*DM];
__device__ __half g_ffh [RT*DFF];
__device__ __half g_memh[RT*DM];
// transposed ([N,K]) fp16 weights
__device__ __half g_wqkvt[3*DM*DM];
__device__ __half g_wq2t [DM*DM];
__device__ __half g_wkvt [2*DM*DM];
__device__ __half g_wo1t [DM*DM];
__device__ __half g_wo2t [DM*DM];
__device__ __half g_fw1t [DFF*DM];
__device__ __half g_fw2t [DM*DFF];

__device__ __forceinline__ uint32_t s2u(const void* p) {
    uint32_t a;
    asm("{ .reg .u64 t; cvta.to.shared.u64 t, %1; cvt.u32.u64 %0, t; }" : "=r"(a) : "l"(p));
    return a;
}
__device__ __forceinline__ uint32_t packh2(float a, float b) {
    __half2 h = __floats2half2_rn(a, b);
    return *(uint32_t*)&h;
}
__device__ __forceinline__ void cp16(uint32_t dst, const void* src) {
    asm volatile("cp.async.ca.shared.global [%0], [%1], 16;" :: "r"(dst), "l"(src));
}
#define CP_COMMIT asm volatile("cp.async.commit_group;")

#define MMA_F16(acc, a0,a1,a2,a3, b0,b1) \
    asm volatile("mma.sync.aligned.m16n8k16.row.col.f32.f16.f16.f32 " \
                 "{%0,%1,%2,%3}, {%4,%5,%6,%7}, {%8,%9}, {%0,%1,%2,%3};" \
                 : "+f"(acc[0]), "+f"(acc[1]), "+f"(acc[2]), "+f"(acc[3]) \
                 : "r"(a0), "r"(a1), "r"(a2), "r"(a3), "r"(b0), "r"(b1))

#define LDSM4(r0,r1,r2,r3, addr) \
    asm volatile("ldmatrix.sync.aligned.m8n8.x4.shared.b16 {%0,%1,%2,%3}, [%4];" \
                 : "=r"(r0), "=r"(r1), "=r"(r2), "=r"(r3) : "r"(addr))
#define LDSM4T(r0,r1,r2,r3, addr) \
    asm volatile("ldmatrix.sync.aligned.m8n8.x4.trans.shared.b16 {%0,%1,%2,%3}, [%4];" \
                 : "=r"(r0), "=r"(r1), "=r"(r2), "=r"(r3) : "r"(addr))

// ---------------- fp16 ldmatrix GEMM ----------------
// C[4096, Nout] = A[4096, K](f16) * Bt[Nout, K](f16)^T
// 128x64 tiles, BK=64 halves (128B SW128 rows), 3-stage cp.async,
// 128 threads (2x2 warps, warp tile 64x32) -> more CTAs for narrow-N GEMMs.
// FUSE: 0=plain (f16 out), 2=bias+relu (f16 out), 3=bias+residual (f32 out)
#define STB 24576                   // bytes per stage (A 16K + B 8K)
#define GSMEM (3*STB)

template<int FUSE>
__global__ void __launch_bounds__(128, 3)
hgemm(const __half* __restrict__ A, const __half* __restrict__ Bt, void* __restrict__ Cv,
      const float* __restrict__ bias, const float* __restrict__ res, int K, int ldc)
{
    extern __shared__ char smem[];
    const uint32_t sb = s2u(smem);
    const int tid = threadIdx.x, lane = tid & 31, wid = tid >> 5;
    const int wm = wid >> 1, wn = wid & 1;       // 2x2 warps
    const int row0 = blockIdx.y * 128, col0 = blockIdx.x * 64;

    auto loadA = [&](int s, int it) {
        const __half* Ag = A + (long long)row0 * K + it * 64;
        const uint32_t d0 = sb + s * STB;
        #pragma unroll
        for (int i = 0; i < 8; i++) {            // 128 rows x 8 chunks / 128 thr
            const int e = tid + i * 128, r = e >> 3, c = e & 7;
            cp16(d0 + r * 128 + ((c ^ (r & 7)) << 4), Ag + (long long)r * K + c * 8);
        }
    };
    auto loadB = [&](int s, int it) {
        const __half* Bg = Bt + (long long)col0 * K + it * 64;
        const uint32_t d0 = sb + s * STB + 16384;
        #pragma unroll
        for (int i = 0; i < 4; i++) {            // 64 rows x 8 chunks / 128 thr
            const int e = tid + i * 128, r = e >> 3, c = e & 7;
            cp16(d0 + r * 128 + ((c ^ (r & 7)) << 4), Bg + (long long)r * K + c * 8);
        }
    };

    float acc[4][4][4];
    #pragma unroll
    for (int i = 0; i < 4; i++)
        #pragma unroll
        for (int j = 0; j < 4; j++)
            #pragma unroll
            for (int q = 0; q < 4; q++) acc[i][j][q] = 0.f;

    const int NIT = K / 64;
    loadA(0, 0); loadB(0, 0); CP_COMMIT;
    loadA(1, 1); loadB(1, 1); CP_COMMIT;

    for (int it = 0; it < NIT; it++) {
        asm volatile("cp.async.wait_group 1;");
        __syncthreads();
        const int j = it + 2;
        if (j < NIT) { loadA(j % 3, j); loadB(j % 3, j); }
        CP_COMMIT;

        const uint32_t sa = sb + (it % 3) * STB;
        const uint32_t sB = sa + 16384;
        #pragma unroll
        for (int kg = 0; kg < 4; kg++) {
            uint32_t af[4][4], bf[4][2];
            #pragma unroll
            for (int mt = 0; mt < 4; mt++) {
                const int r = wm * 64 + mt * 16 + (lane & 7) + ((lane >> 3) & 1) * 8;
                const int ch = kg * 2 + (lane >> 4);
                LDSM4(af[mt][0], af[mt][1], af[mt][2], af[mt][3],
                      sa + r * 128 + ((ch ^ (r & 7)) << 4));
            }
            #pragma unroll
            for (int p = 0; p < 2; p++) {
                const int r = wn * 32 + p * 16 + (lane & 7) + ((lane >> 4) & 1) * 8;
                const int ch = kg * 2 + ((lane >> 3) & 1);
                uint32_t b0, b1, b2, b3;
                LDSM4(b0, b1, b2, b3, sB + r * 128 + ((ch ^ (r & 7)) << 4));
                bf[2*p][0] = b0; bf[2*p][1] = b1; bf[2*p+1][0] = b2; bf[2*p+1][1] = b3;
            }
            #pragma unroll
            for (int mt = 0; mt < 4; mt++)
                #pragma unroll
                for (int nt = 0; nt < 4; nt++)
                    MMA_F16(acc[mt][nt], af[mt][0], af[mt][1], af[mt][2], af[mt][3],
                            bf[nt][0], bf[nt][1]);
        }
    }

    // epilogue
    #pragma unroll
    for (int mt = 0; mt < 4; mt++) {
        #pragma unroll
        for (int nt = 0; nt < 4; nt++) {
            const int r = row0 + wm * 64 + mt * 16 + (lane >> 2);
            const int c = col0 + wn * 32 + nt * 8 + 2 * (lane & 3);
            float v0 = acc[mt][nt][0], v1 = acc[mt][nt][1];
            float v2 = acc[mt][nt][2], v3 = acc[mt][nt][3];
            if (FUSE >= 2) {
                const float b0 = bias[c], b1 = bias[c + 1];
                v0 += b0; v1 += b1; v2 += b0; v3 += b1;
            }
            if (FUSE == 2) {
                v0 = fmaxf(v0, 0.f); v1 = fmaxf(v1, 0.f);
                v2 = fmaxf(v2, 0.f); v3 = fmaxf(v3, 0.f);
            }
            if (FUSE == 3) {
                float* C = (float*)Cv;
                const float2 r0 = *(const float2*)(res + (long long)r * ldc + c);
                const float2 r1 = *(const float2*)(res + (long long)(r + 8) * ldc + c);
                *(float2*)(C + (long long)r * ldc + c)       = make_float2(v0 + r0.x, v1 + r0.y);
                *(float2*)(C + (long long)(r + 8) * ldc + c) = make_float2(v2 + r1.x, v3 + r1.y);
            } else {
                __half* C = (__half*)Cv;
                *(__half2*)(C + (long long)r * ldc + c)       = __floats2half2_rn(v0, v1);
                *(__half2*)(C + (long long)(r + 8) * ldc + c) = __floats2half2_rn(v2, v3);
            }
        }
    }
}

// ---------------- fused flash attention (fp16 MMA + ldmatrix, double-buffered KV) ----------------
// s = (q.k)/8 ; causal j>q -> -inf ; s==0 -> -inf ; softmax ; P.V
#define FBQ  64
#define FBKV 64

template<bool CAUSAL>
__global__ void __launch_bounds__(128, 2)
flash_k(const __half* __restrict__ Qg, const __half* __restrict__ Kg,
        const __half* __restrict__ Vg, __half* __restrict__ Og, int ldq, int ldkv)
{
    __shared__ __align__(128) char sm[32768];   // 2 stages x (8K K + 8K V)
    const uint32_t s0 = s2u(sm);

    const int bz = blockIdx.y;
    const int b = bz / NH, h = bz % NH;
    const int qt = blockIdx.x;
    const int tid = threadIdx.x, lane = tid & 31, w = tid >> 5;
    const int t = lane & 3;
    const int q0 = qt * FBQ;
    const long long rowB = (long long)b * SQ;
    const int hc = h * DK;

    // ---- Q tile -> smem stage0 K area -> A-frags ----
    #pragma unroll
    for (int i = 0; i < 4; i++) {
        const int e = tid + i * 128, r = e >> 3, c = e & 7;
        cp16(s0 + r * 128 + ((c ^ (r & 7)) << 4), Qg + (rowB + q0 + r) * ldq + hc + c * 8);
    }
    CP_COMMIT;
    asm volatile("cp.async.wait_group 0;");
    __syncthreads();
    uint32_t qa[4][4];
    #pragma unroll
    for (int kg = 0; kg < 4; kg++) {
        const int r = w * 16 + (lane & 7) + ((lane >> 3) & 1) * 8;
        const int ch = kg * 2 + (lane >> 4);
        LDSM4(qa[kg][0], qa[kg][1], qa[kg][2], qa[kg][3],
              s0 + r * 128 + ((ch ^ (r & 7)) << 4));
    }
    __syncthreads();

    auto loadKV = [&](int stg, int chk) {
        const int c0 = chk * FBKV;
        const uint32_t sK = s0 + stg * 16384, sV = sK + 8192;
        #pragma unroll
        for (int i = 0; i < 4; i++) {
            const int e = tid + i * 128, r = e >> 3, c = e & 7;
            cp16(sK + r * 128 + ((c ^ (r & 7)) << 4), Kg + (rowB + c0 + r) * ldkv + hc + c * 8);
            cp16(sV + r * 128 + ((c ^ (r & 7)) << 4), Vg + (rowB + c0 + r) * ldkv + hc + c * 8);
        }
    };

    float o[8][4];
    #pragma unroll
    for (int d = 0; d < 8; d++) { o[d][0]=0.f; o[d][1]=0.f; o[d][2]=0.f; o[d][3]=0.f; }
    float m0 = -INFINITY, m1 = -INFINITY, l0 = 0.f, l1 = 0.f;
    const int r0l = q0 + w * 16 + (lane >> 2);
    const int r1l = r0l + 8;

    const int nch = CAUSAL ? (qt + 1) : (SQ / FBKV);
    loadKV(0, 0); CP_COMMIT;

    for (int chk = 0; chk < nch; chk++) {
        const int c0 = chk * FBKV;
        if (chk + 1 < nch) loadKV((chk + 1) & 1, chk + 1);
        CP_COMMIT;
        asm volatile("cp.async.wait_group 1;");
        __syncthreads();
        const uint32_t sK = s0 + (chk & 1) * 16384, sV = sK + 8192;

        // ---- S = Q.K^T ----
        float s[8][4];
        #pragma unroll
        for (int nt = 0; nt < 8; nt++) { s[nt][0]=0.f; s[nt][1]=0.f; s[nt][2]=0.f; s[nt][3]=0.f; }
        #pragma unroll
        for (int kg = 0; kg < 4; kg++) {
            #pragma unroll
            for (int p = 0; p < 4; p++) {
                const int r = p * 16 + (lane & 7) + ((lane >> 4) & 1) * 8;
                const int ch = kg * 2 + ((lane >> 3) & 1);
                uint32_t b0, b1, b2, b3;
                LDSM4(b0, b1, b2, b3, sK + r * 128 + ((ch ^ (r & 7)) << 4));
                MMA_F16(s[2*p],   qa[kg][0], qa[kg][1], qa[kg][2], qa[kg][3], b0, b1);
                MMA_F16(s[2*p+1], qa[kg][0], qa[kg][1], qa[kg][2], qa[kg][3], b2, b3);
            }
        }

        // ---- scale + mask + online softmax ----
        float mx0 = -INFINITY, mx1 = -INFINITY;
        #pragma unroll
        for (int nt = 0; nt < 8; nt++) {
            const int j0 = c0 + nt * 8 + 2 * t, j1 = j0 + 1;
            float v0 = s[nt][0] * 0.125f, v1 = s[nt][1] * 0.125f;
            float v2 = s[nt][2] * 0.125f, v3 = s[nt][3] * 0.125f;
            if ((CAUSAL && j0 > r0l) || v0 == 0.f) v0 = -INFINITY;
            if ((CAUSAL && j1 > r0l) || v1 == 0.f) v1 = -INFINITY;
            if ((CAUSAL && j0 > r1l) || v2 == 0.f) v2 = -INFINITY;
            if ((CAUSAL && j1 > r1l) || v3 == 0.f) v3 = -INFINITY;
            s[nt][0] = v0; s[nt][1] = v1; s[nt][2] = v2; s[nt][3] = v3;
            mx0 = fmaxf(mx0, fmaxf(v0, v1));
            mx1 = fmaxf(mx1, fmaxf(v2, v3));
        }
        mx0 = fmaxf(mx0, __shfl_xor_sync(0xffffffffu, mx0, 1));
        mx0 = fmaxf(mx0, __shfl_xor_sync(0xffffffffu, mx0, 2));
        mx1 = fmaxf(mx1, __shfl_xor_sync(0xffffffffu, mx1, 1));
        mx1 = fmaxf(mx1, __shfl_xor_sync(0xffffffffu, mx1, 2));
        const float mn0 = fmaxf(m0, mx0), mn1 = fmaxf(m1, mx1);
        const float sc0 = __expf(m0 - mn0), sc1 = __expf(m1 - mn1);

        float ps0 = 0.f, ps1 = 0.f;
        #pragma unroll
        for (int nt = 0; nt < 8; nt++) {
            const float p0 = __expf(s[nt][0] - mn0);
            const float p1 = __expf(s[nt][1] - mn0);
            const float p2 = __expf(s[nt][2] - mn1);
            const float p3 = __expf(s[nt][3] - mn1);
            s[nt][0] = p0; s[nt][1] = p1; s[nt][2] = p2; s[nt][3] = p3;
            ps0 += p0 + p1; ps1 += p2 + p3;
        }
        ps0 += __shfl_xor_sync(0xffffffffu, ps0, 1);
        ps0 += __shfl_xor_sync(0xffffffffu, ps0, 2);
        ps1 += __shfl_xor_sync(0xffffffffu, ps1, 1);
        ps1 += __shfl_xor_sync(0xffffffffu, ps1, 2);
        l0 = l0 * sc0 + ps0; l1 = l1 * sc1 + ps1;
        m0 = mn0; m1 = mn1;
        #pragma unroll
        for (int d = 0; d < 8; d++) {
            o[d][0] *= sc0; o[d][1] *= sc0; o[d][2] *= sc1; o[d][3] *= sc1;
        }

        // ---- O += P.V ----
        #pragma unroll
        for (int kg = 0; kg < 4; kg++) {
            const uint32_t a0 = packh2(s[2*kg][0],   s[2*kg][1]);
            const uint32_t a1 = packh2(s[2*kg][2],   s[2*kg][3]);
            const uint32_t a2 = packh2(s[2*kg+1][0], s[2*kg+1][1]);
            const uint32_t a3 = packh2(s[2*kg+1][2], s[2*kg+1][3]);
            #pragma unroll
            for (int p = 0; p < 4; p++) {
                const int r = kg * 16 + (lane & 7) + ((lane >> 3) & 1) * 8;
                const int ch = p * 2 + (lane >> 4);
                uint32_t v0, v1, v2, v3;
                LDSM4T(v0, v1, v2, v3, sV + r * 128 + ((ch ^ (r & 7)) << 4));
                MMA_F16(o[2*p],   a0, a1, a2, a3, v0, v1);
                MMA_F16(o[2*p+1], a0, a1, a2, a3, v2, v3);
            }
        }
        __syncthreads();
    }

    const float i0 = 1.f / l0, i1 = 1.f / l1;
    #pragma unroll
    for (int d = 0; d < 8; d++) {
        const int c = hc + d * 8 + 2 * t;
        *(__half2*)(Og + (rowB + r0l) * DM + c) = __floats2half2_rn(o[d][0] * i0, o[d][1] * i0);
        *(__half2*)(Og + (rowB + r1l) * DM + c) = __floats2half2_rn(o[d][2] * i1, o[d][3] * i1);
    }
}

// ---------------- LayerNorm: warp-per-row (fp32 in, fp16 out) ----------------
__global__ __launch_bounds__(256) void ln_k(const float* __restrict__ in,
                                            const float* __restrict__ al,
                                            const float* __restrict__ be,
                                            __half* __restrict__ out)
{
    const int w = threadIdx.x >> 5, l = threadIdx.x & 31;
    const long long row = (long long)blockIdx.x * 8 + w;
    const float* ip = in + row * DM;

    float4 v[4];
    #pragma unroll
    for (int i = 0; i < 4; i++) v[i] = *(const float4*)(ip + (i * 32 + l) * 4);

    float s = 0.f;
    #pragma unroll
    for (int i = 0; i < 4; i++) s += v[i].x + v[i].y + v[i].z + v[i].w;
    #pragma unroll
    for (int o = 16; o; o >>= 1) s += __shfl_xor_sync(0xffffffffu, s, o);
    const float mu = s * (1.f / DM);

    float ss = 0.f;
    #pragma unroll
    for (int i = 0; i < 4; i++) {
        const float a = v[i].x - mu, b2 = v[i].y - mu, c = v[i].z - mu, d = v[i].w - mu;
        ss += a * a + b2 * b2 + c * c + d * d;
    }
    #pragma unroll
    for (int o = 16; o; o >>= 1) ss += __shfl_xor_sync(0xffffffffu, ss, o);
    const float sd  = sqrtf(ss * (1.f / (DM - 1)));
    const float inv = 1.f / (sd + EPSF);

    #pragma unroll
    for (int i = 0; i < 4; i++) {
        const int c4 = (i * 32 + l) * 4;
        const float4 a4 = *(const float4*)(al + c4);
        const float4 b4 = *(const float4*)(be + c4);
        __half2 h0 = __floats2half2_rn(a4.x * (v[i].x - mu) * inv + b4.x,
                                       a4.y * (v[i].y - mu) * inv + b4.y);
        __half2 h1 = __floats2half2_rn(a4.z * (v[i].z - mu) * inv + b4.z,
                                       a4.w * (v[i].w - mu) * inv + b4.w);
        uint2 pk = make_uint2(*(uint32_t*)&h0, *(uint32_t*)&h1);
        *(uint2*)(out + row * DM + c4) = pk;
    }
}

// ---------------- prep kernels ----------------
struct TrBatch { const float* src[8]; __half* dst[8]; };

__global__ __launch_bounds__(256) void tr8_k(TrBatch tb)
{
    __shared__ float t[32][33];
    const float* src = tb.src[blockIdx.z];
    __half* dst = tb.dst[blockIdx.z];
    const int nb = blockIdx.x*32, kb = blockIdx.y*32;
    const int tx = threadIdx.x & 31, ty = threadIdx.x >> 5;
    #pragma unroll
    for (int i = 0; i < 32; i += 8)
        t[ty+i][tx] = src[(long long)(kb+ty+i)*DM + nb+tx];
    __syncthreads();
    #pragma unroll
    for (int i = 0; i < 32; i += 8)
        dst[(long long)(nb+ty+i)*DM + kb+tx] = __float2half(t[tx][ty+i]);
}

__global__ __launch_bounds__(256) void tr_k(const float* __restrict__ src,
                                            __half* __restrict__ dst, int Kd, int Nd)
{
    __shared__ float t[32][33];
    const int nb = blockIdx.x*32, kb = blockIdx.y*32;
    const int tx = threadIdx.x & 31, ty = threadIdx.x >> 5;
    #pragma unroll
    for (int i = 0; i < 32; i += 8)
        t[ty+i][tx] = src[(long long)(kb+ty+i)*Nd + nb+tx];
    __syncthreads();
    #pragma unroll
    for (int i = 0; i < 32; i += 8)
        dst[(long long)(nb+ty+i)*Kd + kb+tx] = __float2half(t[tx][ty+i]);
}

__global__ void rc_k(const float* __restrict__ src, __half* __restrict__ dst, int n)
{
    const int i = blockIdx.x*256 + threadIdx.x;
    if (i < n) dst[i] = __float2half(src[i]);
}

// ---------------- launch ----------------
extern "C" void kernel_launch(void* const* d_in, const int* in_sizes, int n_in,
                              void* d_out, int out_size)
{
    const float* x    = (const float*)d_in[0];
    const float* mem  = (const float*)d_in[1];
    const float* ln1a = (const float*)d_in[2];
    const float* ln1b = (const float*)d_in[3];
    const float* ln2a = (const float*)d_in[4];
    const float* ln2b = (const float*)d_in[5];
    const float* ln3a = (const float*)d_in[6];
    const float* ln3b = (const float*)d_in[7];
    const float* wq1  = (const float*)d_in[8];
    const float* wk1  = (const float*)d_in[9];
    const float* wv1  = (const float*)d_in[10];
    const float* wo1  = (const float*)d_in[11];
    const float* bo1  = (const float*)d_in[12];
    const float* wq2  = (const float*)d_in[13];
    const float* wk2  = (const float*)d_in[14];
    const float* wv2  = (const float*)d_in[15];
    const float* wo2  = (const float*)d_in[16];
    const float* bo2  = (const float*)d_in[17];
    const float* fw1  = (const float*)d_in[18];
    const float* fb1  = (const float*)d_in[19];
    const float* fw2  = (const float*)d_in[20];
    const float* fb2  = (const float*)d_in[21];
    float* out = (float*)d_out;

    float* px;
    __half *px2h,*pqkvh,*pqh,*pkvh,*pctxh,*pffh,*pmemh;
    __half *pwqkvt,*pwq2t,*pwkvt,*pwo1t,*pwo2t,*pfw1t,*pfw2t;
    cudaGetSymbolAddress((void**)&px,    g_x);
    cudaGetSymbolAddress((void**)&px2h,  g_x2h);
    cudaGetSymbolAddress((void**)&pqkvh, g_qkvh);
    cudaGetSymbolAddress((void**)&pqh,   g_qh);
    cudaGetSymbolAddress((void**)&pkvh,  g_kvh);
    cudaGetSymbolAddress((void**)&pctxh, g_ctxh);
    cudaGetSymbolAddress((void**)&pffh,  g_ffh);
    cudaGetSymbolAddress((void**)&pmemh, g_memh);
    cudaGetSymbolAddress((void**)&pwqkvt,g_wqkvt);
    cudaGetSymbolAddress((void**)&pwq2t, g_wq2t);
    cudaGetSymbolAddress((void**)&pwkvt, g_wkvt);
    cudaGetSymbolAddress((void**)&pwo1t, g_wo1t);
    cudaGetSymbolAddress((void**)&pwo2t, g_wo2t);
    cudaGetSymbolAddress((void**)&pfw1t, g_fw1t);
    cudaGetSymbolAddress((void**)&pfw2t, g_fw2t);

    cudaFuncSetAttribute(hgemm<0>, cudaFuncAttributeMaxDynamicSharedMemorySize, GSMEM);
    cudaFuncSetAttribute(hgemm<2>, cudaFuncAttributeMaxDynamicSharedMemorySize, GSMEM);
    cudaFuncSetAttribute(hgemm<3>, cudaFuncAttributeMaxDynamicSharedMemorySize, GSMEM);

    static cudaStream_t sSide = nullptr;
    static cudaEvent_t  eFork = nullptr, eW = nullptr, eSide = nullptr;
    if (!sSide) {
        cudaStreamCreateWithFlags(&sSide, cudaStreamNonBlocking);
        cudaEventCreateWithFlags(&eFork, cudaEventDisableTiming);
        cudaEventCreateWithFlags(&eW,    cudaEventDisableTiming);
        cudaEventCreateWithFlags(&eSide, cudaEventDisableTiming);
    }

    // ---- fork: side chain (weight prep + mem convert + cross-KV projection) ----
    cudaEventRecord(eFork, 0);
    cudaStreamWaitEvent(sSide, eFork, 0);

    TrBatch tb8;
    tb8.src[0] = wq1; tb8.dst[0] = pwqkvt + 0*DM*DM;
    tb8.src[1] = wk1; tb8.dst[1] = pwqkvt + 1*DM*DM;
    tb8.src[2] = wv1; tb8.dst[2] = pwqkvt + 2*DM*DM;
    tb8.src[3] = wq2; tb8.dst[3] = pwq2t;
    tb8.src[4] = wk2; tb8.dst[4] = pwkvt + 0*DM*DM;
    tb8.src[5] = wv2; tb8.dst[5] = pwkvt + 1*DM*DM;
    tb8.src[6] = wo1; tb8.dst[6] = pwo1t;
    tb8.src[7] = wo2; tb8.dst[7] = pwo2t;
    tr8_k<<<dim3(16, 16, 8), 256, 0, sSide>>>(tb8);
    cudaEventRecord(eW, sSide);                      // square weights ready
    tr_k<<<dim3(DFF/32, DM/32), 256, 0, sSide>>>(fw1, pfw1t, DM, DFF);
    tr_k<<<dim3(DM/32, DFF/32), 256, 0, sSide>>>(fw2, pfw2t, DFF, DM);
    rc_k<<<(RT*DM+255)/256, 256, 0, sSide>>>(mem, pmemh, RT*DM);
    hgemm<0><<<dim3(16, 32), 128, GSMEM, sSide>>>(pmemh, pwkvt, pkvh, nullptr, nullptr, DM, 2*DM);
    cudaEventRecord(eSide, sSide);                   // kv + FFN weights ready

    const dim3 gQKV(24, 32), gP(8, 32), gFF1(32, 32);
    const dim3 gFlash(SQ/FBQ, NB*NH);

    // ---- main chain ----
    // self attention (residual read directly from input x; writes px)
    ln_k<<<RT/8, 256>>>(x, ln1a, ln1b, px2h);
    cudaStreamWaitEvent(0, eW, 0);
    hgemm<0><<<gQKV, 128, GSMEM>>>(px2h, pwqkvt, pqkvh, nullptr, nullptr, DM, 3*DM);
    flash_k<true><<<gFlash, 128>>>(pqkvh, pqkvh + DM, pqkvh + 2*DM, pctxh, 3*DM, 3*DM);
    hgemm<3><<<gP, 128, GSMEM>>>(pctxh, pwo1t, px, bo1, x, DM, DM);

    // cross attention
    ln_k<<<RT/8, 256>>>(px, ln2a, ln2b, px2h);
    hgemm<0><<<gP, 128, GSMEM>>>(px2h, pwq2t, pqh, nullptr, nullptr, DM, DM);
    cudaStreamWaitEvent(0, eSide, 0);
    flash_k<false><<<gFlash, 128>>>(pqh, pkvh, pkvh + DM, pctxh, DM, 2*DM);
    hgemm<3><<<gP, 128, GSMEM>>>(pctxh, pwo2t, px, bo2, px, DM, DM);

    // feed forward
    ln_k<<<RT/8, 256>>>(px, ln3a, ln3b, px2h);
    hgemm<2><<<gFF1, 128, GSMEM>>>(px2h, pfw1t, pffh, fb1, nullptr, DM, DFF);
    hgemm<3><<<gP, 128, GSMEM>>>(pffh, pfw2t, out, fb2, px, DFF, DM);
}